// round 1
// baseline (speedup 1.0000x reference)
#include <cuda_runtime.h>
#include <cstdint>

// Problem constants
#define BATCH   2
#define SEQ     2048
#define HID     1024
#define NHEAD   16
#define HDIM    64
#define QKV_N   (3 * HID)     // 3072
#define M_TOT   (BATCH * SEQ) // 4096

// Scratch (device globals: allocation-free rule)
__device__ float g_qkv[(size_t)M_TOT * QKV_N]; // [4096, 3072]
__device__ float g_ctx[(size_t)M_TOT * HID];   // [4096, 1024]

// ---------------------------------------------------------------------------
// Tiled fp32 GEMM with bias: C[M,N] = A[M,K] @ B[K,N] + bias[N]
// BM=BN=64, BK=16, 256 threads, 4x4 microtile per thread.
// ---------------------------------------------------------------------------
__global__ __launch_bounds__(256) void gemm_bias_kernel(
    const float* __restrict__ A, const float* __restrict__ B,
    const float* __restrict__ bias, float* __restrict__ C,
    int M, int N, int K)
{
    __shared__ float As[16][68];  // [k][m], padded
    __shared__ float Bs[16][68];  // [k][n], padded

    const int tid = threadIdx.x;
    const int ty = tid >> 4;      // 0..15
    const int tx = tid & 15;      // 0..15
    const int m0 = blockIdx.y * 64;
    const int n0 = blockIdx.x * 64;

    // A-tile loader coords: thread -> (m, k4)
    const int a_m  = tid >> 2;         // 0..63
    const int a_k4 = (tid & 3) * 4;    // 0,4,8,12
    // B-tile loader coords: thread -> (k, n4)
    const int b_k  = tid >> 4;         // 0..15
    const int b_n4 = (tid & 15) * 4;   // 0..60

    const float* Aptr = A + (size_t)(m0 + a_m) * K + a_k4;
    const float* Bptr = B + (size_t)b_k * N + n0 + b_n4;

    float acc[4][4];
#pragma unroll
    for (int i = 0; i < 4; i++)
#pragma unroll
        for (int j = 0; j < 4; j++) acc[i][j] = 0.0f;

    for (int k0 = 0; k0 < K; k0 += 16) {
        float4 av = *(const float4*)(Aptr + k0);
        float4 bv = *(const float4*)(Bptr + (size_t)k0 * N);
        As[a_k4 + 0][a_m] = av.x;
        As[a_k4 + 1][a_m] = av.y;
        As[a_k4 + 2][a_m] = av.z;
        As[a_k4 + 3][a_m] = av.w;
        *(float4*)&Bs[b_k][b_n4] = bv;
        __syncthreads();

#pragma unroll
        for (int kk = 0; kk < 16; kk++) {
            float4 a = *(const float4*)&As[kk][ty * 4];
            float4 b = *(const float4*)&Bs[kk][tx * 4];
            acc[0][0] += a.x * b.x; acc[0][1] += a.x * b.y; acc[0][2] += a.x * b.z; acc[0][3] += a.x * b.w;
            acc[1][0] += a.y * b.x; acc[1][1] += a.y * b.y; acc[1][2] += a.y * b.z; acc[1][3] += a.y * b.w;
            acc[2][0] += a.z * b.x; acc[2][1] += a.z * b.y; acc[2][2] += a.z * b.z; acc[2][3] += a.z * b.w;
            acc[3][0] += a.w * b.x; acc[3][1] += a.w * b.y; acc[3][2] += a.w * b.z; acc[3][3] += a.w * b.w;
        }
        __syncthreads();
    }

    const float4 bias4 = *(const float4*)(bias + n0 + tx * 4);
#pragma unroll
    for (int i = 0; i < 4; i++) {
        float4 out;
        out.x = acc[i][0] + bias4.x;
        out.y = acc[i][1] + bias4.y;
        out.z = acc[i][2] + bias4.z;
        out.w = acc[i][3] + bias4.w;
        *(float4*)(C + (size_t)(m0 + ty * 4 + i) * N + n0 + tx * 4) = out;
    }
}

// ---------------------------------------------------------------------------
// Flash attention over the packed qkv buffer [4096, 3072].
// Q(b,h,s,d) = qkv[(b*SEQ+s)*3072 + h*64 + d]; K at +1024; V at +2048.
// Block: (q_tile=64, head, batch). 256 threads: ty=tid/16 (row group of 4),
// tx=tid%16 (2 score cols / 4 out dims). BK=32 keys per iteration.
// Output ctx in merged-head layout [B,S,H].
// ---------------------------------------------------------------------------
__device__ __forceinline__ float warp16_max(float v) {
#pragma unroll
    for (int off = 8; off >= 1; off >>= 1)
        v = fmaxf(v, __shfl_xor_sync(0xffffffffu, v, off));
    return v;
}
__device__ __forceinline__ float warp16_sum(float v) {
#pragma unroll
    for (int off = 8; off >= 1; off >>= 1)
        v += __shfl_xor_sync(0xffffffffu, v, off);
    return v;
}

__global__ __launch_bounds__(256) void flash_attn_kernel(
    const float* __restrict__ qkv, const float* __restrict__ mask,
    float* __restrict__ ctx)
{
    __shared__ float Qs[64][68];
    __shared__ float Ks[32][68];
    __shared__ float Vs[32][68];
    __shared__ float Ps[64][36];

    const int tid = threadIdx.x;
    const int ty = tid >> 4;
    const int tx = tid & 15;
    const int q0 = blockIdx.x * 64;
    const int h  = blockIdx.y;
    const int b  = blockIdx.z;

    const size_t row_base = (size_t)b * SEQ;
    const int hoff = h * HDIM;

    // Load Q tile (pre-scaled by 1/sqrt(64) = 0.125)
#pragma unroll
    for (int it = 0; it < 4; it++) {
        int idx = tid + it * 256;            // 0..1023
        int r  = idx >> 4;                    // 0..63
        int c4 = (idx & 15) * 4;              // 0..60
        float4 v = *(const float4*)(qkv + (row_base + q0 + r) * QKV_N + hoff + c4);
        v.x *= 0.125f; v.y *= 0.125f; v.z *= 0.125f; v.w *= 0.125f;
        *(float4*)&Qs[r][c4] = v;
    }

    float mrow[4], lrow[4];
    float4 Oacc[4];
#pragma unroll
    for (int i = 0; i < 4; i++) {
        mrow[i] = -1e30f;
        lrow[i] = 0.0f;
        Oacc[i] = make_float4(0.f, 0.f, 0.f, 0.f);
    }

    for (int k0 = 0; k0 < SEQ; k0 += 32) {
        // Load K and V tiles (32 rows x 64 dims each)
#pragma unroll
        for (int it = 0; it < 2; it++) {
            int idx = tid + it * 256;        // 0..511
            int r  = idx >> 4;                // 0..31
            int c4 = (idx & 15) * 4;
            size_t base = (row_base + k0 + r) * QKV_N + hoff + c4;
            *(float4*)&Ks[r][c4] = *(const float4*)(qkv + base + HID);
            *(float4*)&Vs[r][c4] = *(const float4*)(qkv + base + 2 * HID);
        }
        __syncthreads();

        // Scores: s[i][j] for rows ty*4+i, cols tx*2+j
        float4 sacc[4][2];
#pragma unroll
        for (int i = 0; i < 4; i++)
#pragma unroll
            for (int j = 0; j < 2; j++) sacc[i][j] = make_float4(0.f, 0.f, 0.f, 0.f);

#pragma unroll
        for (int d4 = 0; d4 < 16; d4++) {
            float4 kk0 = *(const float4*)&Ks[tx * 2 + 0][d4 * 4];
            float4 kk1 = *(const float4*)&Ks[tx * 2 + 1][d4 * 4];
#pragma unroll
            for (int i = 0; i < 4; i++) {
                float4 q = *(const float4*)&Qs[ty * 4 + i][d4 * 4];
                sacc[i][0].x += q.x * kk0.x; sacc[i][0].y += q.y * kk0.y;
                sacc[i][0].z += q.z * kk0.z; sacc[i][0].w += q.w * kk0.w;
                sacc[i][1].x += q.x * kk1.x; sacc[i][1].y += q.y * kk1.y;
                sacc[i][1].z += q.z * kk1.z; sacc[i][1].w += q.w * kk1.w;
            }
        }

        float mv0 = mask[(size_t)b * SEQ + k0 + tx * 2 + 0];
        float mv1 = mask[(size_t)b * SEQ + k0 + tx * 2 + 1];

        float s[4][2];
#pragma unroll
        for (int i = 0; i < 4; i++) {
            s[i][0] = sacc[i][0].x + sacc[i][0].y + sacc[i][0].z + sacc[i][0].w + mv0;
            s[i][1] = sacc[i][1].x + sacc[i][1].y + sacc[i][1].z + sacc[i][1].w + mv1;
        }

        float alpha[4];
#pragma unroll
        for (int i = 0; i < 4; i++) {
            float tmax = warp16_max(fmaxf(s[i][0], s[i][1]));
            float newm = fmaxf(mrow[i], tmax);
            alpha[i] = __expf(mrow[i] - newm);
            float p0 = __expf(s[i][0] - newm);
            float p1 = __expf(s[i][1] - newm);
            float rsum = warp16_sum(p0 + p1);
            lrow[i] = lrow[i] * alpha[i] + rsum;
            mrow[i] = newm;
            Ps[ty * 4 + i][tx * 2 + 0] = p0;
            Ps[ty * 4 + i][tx * 2 + 1] = p1;
            Oacc[i].x *= alpha[i]; Oacc[i].y *= alpha[i];
            Oacc[i].z *= alpha[i]; Oacc[i].w *= alpha[i];
        }
        __syncthreads();

        // O += P @ V   (dims d = tx*4 .. tx*4+3)
#pragma unroll
        for (int k = 0; k < 32; k++) {
            float4 v = *(const float4*)&Vs[k][tx * 4];
#pragma unroll
            for (int i = 0; i < 4; i++) {
                float p = Ps[ty * 4 + i][k];
                Oacc[i].x += p * v.x; Oacc[i].y += p * v.y;
                Oacc[i].z += p * v.z; Oacc[i].w += p * v.w;
            }
        }
        __syncthreads();
    }

    // Finalize and store to ctx[b, s, h*64 + d]
#pragma unroll
    for (int i = 0; i < 4; i++) {
        float inv = 1.0f / lrow[i];
        float4 o = Oacc[i];
        o.x *= inv; o.y *= inv; o.z *= inv; o.w *= inv;
        *(float4*)(ctx + (row_base + q0 + ty * 4 + i) * HID + hoff + tx * 4) = o;
    }
}

// ---------------------------------------------------------------------------
extern "C" void kernel_launch(void* const* d_in, const int* in_sizes, int n_in,
                              void* d_out, int out_size)
{
    const float* hidden = (const float*)d_in[0];
    const float* mask   = (const float*)d_in[1];
    const float* w_attn = (const float*)d_in[2];
    const float* b_attn = (const float*)d_in[3];
    const float* w_proj = (const float*)d_in[4];
    const float* b_proj = (const float*)d_in[5];
    float* out = (float*)d_out;

    float* qkv = nullptr;
    float* ctx = nullptr;
    cudaGetSymbolAddress((void**)&qkv, g_qkv);
    cudaGetSymbolAddress((void**)&ctx, g_ctx);

    // 1) QKV = hidden @ c_attn_w + b   [4096, 3072]
    gemm_bias_kernel<<<dim3(QKV_N / 64, M_TOT / 64), 256>>>(
        hidden, w_attn, b_attn, qkv, M_TOT, QKV_N, HID);

    // 2) Flash attention -> ctx [4096, 1024] (merged heads)
    flash_attn_kernel<<<dim3(SEQ / 64, NHEAD, BATCH), 256>>>(qkv, mask, ctx);

    // 3) out = ctx @ c_proj_w + b   [4096, 1024]
    gemm_bias_kernel<<<dim3(HID / 64, M_TOT / 64), 256>>>(
        ctx, w_proj, b_proj, out, M_TOT, HID, HID);
}

// round 2
// speedup vs baseline: 1.2662x; 1.2662x over previous
#include <cuda_runtime.h>
#include <cstdint>

// Problem constants
#define BATCH   2
#define SEQ     2048
#define HID     1024
#define NHEAD   16
#define HDIM    64
#define QKV_N   (3 * HID)     // 3072
#define M_TOT   (BATCH * SEQ) // 4096

// Scratch (device globals: allocation-free rule)
__device__ float g_qkv[(size_t)M_TOT * QKV_N]; // [4096, 3072]
__device__ float g_ctx[(size_t)M_TOT * HID];   // [4096, 1024]

// ---------------------------------------------------------------------------
// Tiled fp32 GEMM with bias: C[M,N] = A[M,K] @ B[K,N] + bias[N]
// BM=BN=128, BK=8, 256 threads, 8x8 microtile per thread, reg prefetch.
// ---------------------------------------------------------------------------
__global__ __launch_bounds__(256) void gemm_bias_128(
    const float* __restrict__ A, const float* __restrict__ B,
    const float* __restrict__ bias, float* __restrict__ C,
    int M, int N, int K)
{
    __shared__ float As[8][132];  // [k][m], padded (132) for conflict-free T-store
    __shared__ float Bs[8][128];  // [k][n]

    const int tid = threadIdx.x;
    const int tx = tid & 15;      // 0..15 -> n microtile
    const int ty = tid >> 4;      // 0..15 -> m microtile
    const int m0 = blockIdx.y * 128;
    const int n0 = blockIdx.x * 128;

    // A loader: thread -> (row, k4)
    const int a_row = tid >> 1;        // 0..127
    const int a_k4  = (tid & 1) * 4;   // 0 or 4
    // B loader: thread -> (k, col4)
    const int b_k   = tid >> 5;        // 0..7
    const int b_c4  = (tid & 31) * 4;  // 0..124

    const float* Aptr = A + (size_t)(m0 + a_row) * K + a_k4;
    const float* Bptr = B + (size_t)b_k * N + n0 + b_c4;

    float acc[8][8];
#pragma unroll
    for (int i = 0; i < 8; i++)
#pragma unroll
        for (int j = 0; j < 8; j++) acc[i][j] = 0.0f;

    float4 av = *(const float4*)Aptr;
    float4 bv = *(const float4*)Bptr;

    for (int k0 = 0; k0 < K; k0 += 8) {
        As[a_k4 + 0][a_row] = av.x;
        As[a_k4 + 1][a_row] = av.y;
        As[a_k4 + 2][a_row] = av.z;
        As[a_k4 + 3][a_row] = av.w;
        *(float4*)&Bs[b_k][b_c4] = bv;
        __syncthreads();

        if (k0 + 8 < K) {
            av = *(const float4*)(Aptr + k0 + 8);
            bv = *(const float4*)(Bptr + (size_t)(k0 + 8) * N);
        }

#pragma unroll
        for (int kk = 0; kk < 8; kk++) {
            float4 a0 = *(const float4*)&As[kk][ty * 4];
            float4 a1 = *(const float4*)&As[kk][64 + ty * 4];
            float4 b0 = *(const float4*)&Bs[kk][tx * 4];
            float4 b1 = *(const float4*)&Bs[kk][64 + tx * 4];
            float a[8] = {a0.x, a0.y, a0.z, a0.w, a1.x, a1.y, a1.z, a1.w};
            float bb[8] = {b0.x, b0.y, b0.z, b0.w, b1.x, b1.y, b1.z, b1.w};
#pragma unroll
            for (int i = 0; i < 8; i++)
#pragma unroll
                for (int j = 0; j < 8; j++)
                    acc[i][j] += a[i] * bb[j];
        }
        __syncthreads();
    }

    const float4 bias0 = *(const float4*)(bias + n0 + tx * 4);
    const float4 bias1 = *(const float4*)(bias + n0 + 64 + tx * 4);

#pragma unroll
    for (int ih = 0; ih < 2; ih++) {
#pragma unroll
        for (int i = 0; i < 4; i++) {
            const int row = m0 + ih * 64 + ty * 4 + i;
            float4 o0, o1;
            o0.x = acc[ih * 4 + i][0] + bias0.x;
            o0.y = acc[ih * 4 + i][1] + bias0.y;
            o0.z = acc[ih * 4 + i][2] + bias0.z;
            o0.w = acc[ih * 4 + i][3] + bias0.w;
            o1.x = acc[ih * 4 + i][4] + bias1.x;
            o1.y = acc[ih * 4 + i][5] + bias1.y;
            o1.z = acc[ih * 4 + i][6] + bias1.z;
            o1.w = acc[ih * 4 + i][7] + bias1.w;
            *(float4*)(C + (size_t)row * N + n0 + tx * 4) = o0;
            *(float4*)(C + (size_t)row * N + n0 + 64 + tx * 4) = o1;
        }
    }
}

// ---------------------------------------------------------------------------
// Flash attention, GEMM-shaped: 64 q-rows x 64 keys per tile, 256 threads,
// 4x4 scores + 4x4 output per thread. Q,K transposed in SMEM ([d][m]),
// V natural ([k][d]), P aliases the K buffer. 48KB static SMEM exactly.
// ---------------------------------------------------------------------------
__device__ __forceinline__ float warp16_max(float v) {
#pragma unroll
    for (int off = 8; off >= 1; off >>= 1)
        v = fmaxf(v, __shfl_xor_sync(0xffffffffu, v, off));
    return v;
}
__device__ __forceinline__ float warp16_sum(float v) {
#pragma unroll
    for (int off = 8; off >= 1; off >>= 1)
        v += __shfl_xor_sync(0xffffffffu, v, off);
    return v;
}

__global__ __launch_bounds__(256) void flash_attn_kernel(
    const float* __restrict__ qkv, const float* __restrict__ mask,
    float* __restrict__ ctx)
{
    __shared__ float QsT[64][64]; // [d][m], Q transposed, pre-scaled
    __shared__ float KP[64][64];  // scores: KsT [d][n]; PV: Ps [m][k]
    __shared__ float Vs[64][64];  // [k][d]

    const int tid = threadIdx.x;
    const int tx = tid & 15;
    const int ty = tid >> 4;
    const int q0 = blockIdx.x * 64;
    const int h  = blockIdx.y;
    const int b  = blockIdx.z;

    const size_t row_base = (size_t)b * SEQ;
    const int hoff = h * HDIM;

    // Scattered mapping for transposed stores: lane -> row, warp -> col group.
    const int lr = tid & 63;  // row within tile (conflict-free T-store: bank=lr)
    const int lc = tid >> 6;  // 0..3 col-quad group

    // Load Q tile transposed, pre-scaled by 1/sqrt(64)=0.125
#pragma unroll
    for (int it = 0; it < 4; it++) {
        const int c4 = (lc + it * 4) * 4; // 0..60
        float4 v = *(const float4*)(qkv + (row_base + q0 + lr) * QKV_N + hoff + c4);
        QsT[c4 + 0][lr] = v.x * 0.125f;
        QsT[c4 + 1][lr] = v.y * 0.125f;
        QsT[c4 + 2][lr] = v.z * 0.125f;
        QsT[c4 + 3][lr] = v.w * 0.125f;
    }

    float mrow[4], lrow[4];
    float4 Oacc[4];
#pragma unroll
    for (int i = 0; i < 4; i++) {
        mrow[i] = -1e30f;
        lrow[i] = 0.0f;
        Oacc[i] = make_float4(0.f, 0.f, 0.f, 0.f);
    }

    for (int k0 = 0; k0 < SEQ; k0 += 64) {
        // Load K transposed (scattered mapping) and V natural
#pragma unroll
        for (int it = 0; it < 4; it++) {
            const int c4 = (lc + it * 4) * 4;
            const size_t kbase = (row_base + k0 + lr) * QKV_N + hoff + c4;
            float4 kv = *(const float4*)(qkv + kbase + HID);
            KP[c4 + 0][lr] = kv.x;
            KP[c4 + 1][lr] = kv.y;
            KP[c4 + 2][lr] = kv.z;
            KP[c4 + 3][lr] = kv.w;

            const int idx = tid + it * 256;
            const int vr = idx >> 4;
            const int vc4 = (idx & 15) * 4;
            *(float4*)&Vs[vr][vc4] =
                *(const float4*)(qkv + (row_base + k0 + vr) * QKV_N + hoff + 2 * HID + vc4);
        }
        __syncthreads();

        // Scores: s[i][j], rows ty*4+i, key cols tx*4+j
        float s[4][4];
#pragma unroll
        for (int i = 0; i < 4; i++)
#pragma unroll
            for (int j = 0; j < 4; j++) s[i][j] = 0.0f;

#pragma unroll 8
        for (int d = 0; d < 64; d++) {
            float4 a = *(const float4*)&QsT[d][ty * 4];
            float4 k4 = *(const float4*)&KP[d][tx * 4];
            s[0][0] += a.x * k4.x; s[0][1] += a.x * k4.y; s[0][2] += a.x * k4.z; s[0][3] += a.x * k4.w;
            s[1][0] += a.y * k4.x; s[1][1] += a.y * k4.y; s[1][2] += a.y * k4.z; s[1][3] += a.y * k4.w;
            s[2][0] += a.z * k4.x; s[2][1] += a.z * k4.y; s[2][2] += a.z * k4.z; s[2][3] += a.z * k4.w;
            s[3][0] += a.w * k4.x; s[3][1] += a.w * k4.y; s[3][2] += a.w * k4.z; s[3][3] += a.w * k4.w;
        }

        const float4 mask4 = *(const float4*)(mask + (size_t)b * SEQ + k0 + tx * 4);
#pragma unroll
        for (int i = 0; i < 4; i++) {
            s[i][0] += mask4.x; s[i][1] += mask4.y;
            s[i][2] += mask4.z; s[i][3] += mask4.w;
        }

        // Online softmax bookkeeping
        float alpha[4], p[4][4];
#pragma unroll
        for (int i = 0; i < 4; i++) {
            float tmax = fmaxf(fmaxf(s[i][0], s[i][1]), fmaxf(s[i][2], s[i][3]));
            tmax = warp16_max(tmax);
            const float newm = fmaxf(mrow[i], tmax);
            alpha[i] = __expf(mrow[i] - newm);
            float rs = 0.0f;
#pragma unroll
            for (int j = 0; j < 4; j++) {
                p[i][j] = __expf(s[i][j] - newm);
                rs += p[i][j];
            }
            rs = warp16_sum(rs);
            lrow[i] = lrow[i] * alpha[i] + rs;
            mrow[i] = newm;
        }
        __syncthreads();  // everyone done reading KP (as K) before P overwrite

#pragma unroll
        for (int i = 0; i < 4; i++) {
            *(float4*)&KP[ty * 4 + i][tx * 4] = make_float4(p[i][0], p[i][1], p[i][2], p[i][3]);
            Oacc[i].x *= alpha[i]; Oacc[i].y *= alpha[i];
            Oacc[i].z *= alpha[i]; Oacc[i].w *= alpha[i];
        }
        __syncthreads();  // Ps visible

        // O += P @ V  (rows ty*4+i, dims tx*4..tx*4+3)
#pragma unroll 4
        for (int k4 = 0; k4 < 16; k4++) {
            float4 v0 = *(const float4*)&Vs[k4 * 4 + 0][tx * 4];
            float4 v1 = *(const float4*)&Vs[k4 * 4 + 1][tx * 4];
            float4 v2 = *(const float4*)&Vs[k4 * 4 + 2][tx * 4];
            float4 v3 = *(const float4*)&Vs[k4 * 4 + 3][tx * 4];
#pragma unroll
            for (int i = 0; i < 4; i++) {
                float4 p4 = *(const float4*)&KP[ty * 4 + i][k4 * 4];
                Oacc[i].x += p4.x * v0.x + p4.y * v1.x + p4.z * v2.x + p4.w * v3.x;
                Oacc[i].y += p4.x * v0.y + p4.y * v1.y + p4.z * v2.y + p4.w * v3.y;
                Oacc[i].z += p4.x * v0.z + p4.y * v1.z + p4.z * v2.z + p4.w * v3.z;
                Oacc[i].w += p4.x * v0.w + p4.y * v1.w + p4.z * v2.w + p4.w * v3.w;
            }
        }
        __syncthreads();  // before next tile overwrites KP/Vs
    }

    // Finalize and store ctx[b, s, h*64 + d]
#pragma unroll
    for (int i = 0; i < 4; i++) {
        const float inv = 1.0f / lrow[i];
        float4 o = Oacc[i];
        o.x *= inv; o.y *= inv; o.z *= inv; o.w *= inv;
        *(float4*)(ctx + (row_base + q0 + ty * 4 + i) * HID + hoff + tx * 4) = o;
    }
}

// ---------------------------------------------------------------------------
extern "C" void kernel_launch(void* const* d_in, const int* in_sizes, int n_in,
                              void* d_out, int out_size)
{
    const float* hidden = (const float*)d_in[0];
    const float* mask   = (const float*)d_in[1];
    const float* w_attn = (const float*)d_in[2];
    const float* b_attn = (const float*)d_in[3];
    const float* w_proj = (const float*)d_in[4];
    const float* b_proj = (const float*)d_in[5];
    float* out = (float*)d_out;

    float* qkv = nullptr;
    float* ctx = nullptr;
    cudaGetSymbolAddress((void**)&qkv, g_qkv);
    cudaGetSymbolAddress((void**)&ctx, g_ctx);

    // 1) QKV = hidden @ c_attn_w + b   [4096, 3072]
    gemm_bias_128<<<dim3(QKV_N / 128, M_TOT / 128), 256>>>(
        hidden, w_attn, b_attn, qkv, M_TOT, QKV_N, HID);

    // 2) Flash attention -> ctx [4096, 1024] (merged heads)
    flash_attn_kernel<<<dim3(SEQ / 64, NHEAD, BATCH), 256>>>(qkv, mask, ctx);

    // 3) out = ctx @ c_proj_w + b   [4096, 1024]
    gemm_bias_128<<<dim3(HID / 128, M_TOT / 128), 256>>>(
        ctx, w_proj, b_proj, out, M_TOT, HID, HID);
}

// round 4
// speedup vs baseline: 1.5456x; 1.2207x over previous
#include <cuda_runtime.h>
#include <cuda_bf16.h>
#include <cstdint>

// Problem constants
#define BATCH   2
#define SEQ     2048
#define HID     1024
#define NHEAD   16
#define HDIM    64
#define QKV_N   (3 * HID)     // 3072
#define M_TOT   (BATCH * SEQ) // 4096

// Scratch (device globals: allocation-free rule)
__device__ float g_qkv[(size_t)M_TOT * QKV_N]; // [4096, 3072]
__device__ float g_ctx[(size_t)M_TOT * HID];   // [4096, 1024]
__device__ __nv_bfloat16 g_wTh[(size_t)QKV_N * HID]; // c_attn_w^T hi
__device__ __nv_bfloat16 g_wTl[(size_t)QKV_N * HID]; // c_attn_w^T lo
__device__ __nv_bfloat16 g_pTh[(size_t)HID * HID];   // c_proj_w^T hi
__device__ __nv_bfloat16 g_pTl[(size_t)HID * HID];   // c_proj_w^T lo

// ---------------------------------------------------------------------------
// bf16 split helpers
// ---------------------------------------------------------------------------
__device__ __forceinline__ void split_bf16(float a, __nv_bfloat16& h, __nv_bfloat16& l) {
    h = __float2bfloat16_rn(a);
    l = __float2bfloat16_rn(a - __bfloat162float(h));
}

__device__ __forceinline__ void mma_bf16(
    float& d0, float& d1, float& d2, float& d3,
    uint32_t a0, uint32_t a1, uint32_t a2, uint32_t a3,
    uint32_t b0, uint32_t b1)
{
    asm volatile(
        "mma.sync.aligned.m16n8k16.row.col.f32.bf16.bf16.f32 "
        "{%0,%1,%2,%3}, {%4,%5,%6,%7}, {%8,%9}, {%0,%1,%2,%3};"
        : "+f"(d0), "+f"(d1), "+f"(d2), "+f"(d3)
        : "r"(a0), "r"(a1), "r"(a2), "r"(a3), "r"(b0), "r"(b1));
}

// ---------------------------------------------------------------------------
// Prep: transpose + bf16-split weights: B[K][N] -> Bh/Bl [N][K] bf16
// ---------------------------------------------------------------------------
__global__ void transpose_split(const float* __restrict__ B,
                                __nv_bfloat16* __restrict__ Bh,
                                __nv_bfloat16* __restrict__ Bl,
                                int K, int N)
{
    __shared__ float t[32][33];
    const int n0 = blockIdx.x * 32, k0 = blockIdx.y * 32;
    const int x = threadIdx.x, y = threadIdx.y; // (32,8)
#pragma unroll
    for (int i = y; i < 32; i += 8)
        t[i][x] = B[(size_t)(k0 + i) * N + n0 + x];
    __syncthreads();
#pragma unroll
    for (int i = y; i < 32; i += 8) {
        float a = t[x][i];
        __nv_bfloat16 h, l;
        split_bf16(a, h, l);
        Bh[(size_t)(n0 + i) * K + k0 + x] = h;
        Bl[(size_t)(n0 + i) * K + k0 + x] = l;
    }
}

// ---------------------------------------------------------------------------
// Split-bf16 tensor-core GEMM: C[M,N] = A[M,K] @ Bt[N,K]^T + bias
// Tile 128x128, KC=32, 256 threads = 8 warps (2m x 4n), warp tile 64x32.
// 3 mma passes per fragment pair: Ah*Bh + Ah*Bl + Al*Bh.
// ---------------------------------------------------------------------------
__global__ __launch_bounds__(256, 2) void gemm_bf16s(
    const float* __restrict__ A,
    const __nv_bfloat16* __restrict__ Bth, const __nv_bfloat16* __restrict__ Btl,
    const float* __restrict__ bias, float* __restrict__ C,
    int K, int N)
{
    __shared__ __nv_bfloat16 sAh[128][40];
    __shared__ __nv_bfloat16 sAl[128][40];
    __shared__ __nv_bfloat16 sBh[128][40];
    __shared__ __nv_bfloat16 sBl[128][40];
    __shared__ float sBias[128];

    const int tid = threadIdx.x;
    const int wid = tid >> 5;
    const int lane = tid & 31;
    const int g  = lane >> 2;        // 0..7 (fragment row group)
    const int c2 = (lane & 3) * 2;   // 0,2,4,6 (fragment col pair)
    const int warp_m = wid & 1;      // 0..1
    const int warp_n = wid >> 1;     // 0..3
    const int m0 = blockIdx.y * 128;
    const int n0 = blockIdx.x * 128;

    if (tid < 128) sBias[tid] = bias[n0 + tid];

    float acc[4][4][4];
#pragma unroll
    for (int mi = 0; mi < 4; mi++)
#pragma unroll
        for (int ni = 0; ni < 4; ni++)
#pragma unroll
            for (int r = 0; r < 4; r++) acc[mi][ni][r] = 0.0f;

    const int wm = warp_m * 64;
    const int wn = warp_n * 32;

    const int nchunks = K >> 5;
    for (int ic = 0; ic < nchunks; ic++) {
        const int k0 = ic << 5;

        // ---- Load A chunk (128x32 fp32 -> split bf16) ----
#pragma unroll
        for (int it = 0; it < 4; it++) {
            const int idx = tid + it * 256;   // 0..1023
            const int r = idx >> 3;           // 0..127
            const int q = idx & 7;            // 0..7
            float4 v = *(const float4*)(A + (size_t)(m0 + r) * K + k0 + q * 4);
            __nv_bfloat16 h0, l0, h1, l1, h2, l2, h3, l3;
            split_bf16(v.x, h0, l0); split_bf16(v.y, h1, l1);
            split_bf16(v.z, h2, l2); split_bf16(v.w, h3, l3);
            __nv_bfloat162 ph0 = {h0, h1}, ph1 = {h2, h3};
            __nv_bfloat162 pl0 = {l0, l1}, pl1 = {l2, l3};
            *(__nv_bfloat162*)&sAh[r][q * 4 + 0] = ph0;
            *(__nv_bfloat162*)&sAh[r][q * 4 + 2] = ph1;
            *(__nv_bfloat162*)&sAl[r][q * 4 + 0] = pl0;
            *(__nv_bfloat162*)&sAl[r][q * 4 + 2] = pl1;
        }
        // ---- Load B chunk (pre-split bf16, 128x32 each) ----
#pragma unroll
        for (int it = 0; it < 4; it++) {
            const int idx = tid + it * 256;   // 0..1023
            const int mat = idx >> 9;         // 0:hi 1:lo
            const int j = idx & 511;
            const int r = j >> 2;             // 0..127
            const int q = j & 3;              // 0..3 (8 bf16 units)
            const __nv_bfloat16* src = (mat ? Btl : Bth) + (size_t)(n0 + r) * K + k0 + q * 8;
            uint4 v = *(const uint4*)src;
            if (mat) *(uint4*)&sBl[r][q * 8] = v;
            else     *(uint4*)&sBh[r][q * 8] = v;
        }
        __syncthreads();

        // ---- MMA: two k16 steps ----
#pragma unroll
        for (int kk = 0; kk < 32; kk += 16) {
            uint32_t ah[4][4], al[4][4];
#pragma unroll
            for (int mi = 0; mi < 4; mi++) {
                const int R0 = wm + mi * 16 + g;
                const int R1 = R0 + 8;
                ah[mi][0] = *(const uint32_t*)&sAh[R0][kk + c2];
                ah[mi][1] = *(const uint32_t*)&sAh[R1][kk + c2];
                ah[mi][2] = *(const uint32_t*)&sAh[R0][kk + 8 + c2];
                ah[mi][3] = *(const uint32_t*)&sAh[R1][kk + 8 + c2];
                al[mi][0] = *(const uint32_t*)&sAl[R0][kk + c2];
                al[mi][1] = *(const uint32_t*)&sAl[R1][kk + c2];
                al[mi][2] = *(const uint32_t*)&sAl[R0][kk + 8 + c2];
                al[mi][3] = *(const uint32_t*)&sAl[R1][kk + 8 + c2];
            }
#pragma unroll
            for (int ni = 0; ni < 4; ni++) {
                const int nr = wn + ni * 8 + g;
                const uint32_t bh0 = *(const uint32_t*)&sBh[nr][kk + c2];
                const uint32_t bh1 = *(const uint32_t*)&sBh[nr][kk + 8 + c2];
                const uint32_t bl0 = *(const uint32_t*)&sBl[nr][kk + c2];
                const uint32_t bl1 = *(const uint32_t*)&sBl[nr][kk + 8 + c2];
#pragma unroll
                for (int mi = 0; mi < 4; mi++) {
                    mma_bf16(acc[mi][ni][0], acc[mi][ni][1], acc[mi][ni][2], acc[mi][ni][3],
                             ah[mi][0], ah[mi][1], ah[mi][2], ah[mi][3], bh0, bh1);
                    mma_bf16(acc[mi][ni][0], acc[mi][ni][1], acc[mi][ni][2], acc[mi][ni][3],
                             ah[mi][0], ah[mi][1], ah[mi][2], ah[mi][3], bl0, bl1);
                    mma_bf16(acc[mi][ni][0], acc[mi][ni][1], acc[mi][ni][2], acc[mi][ni][3],
                             al[mi][0], al[mi][1], al[mi][2], al[mi][3], bh0, bh1);
                }
            }
        }
        __syncthreads();
    }

    // ---- Epilogue: bias + store ----
#pragma unroll
    for (int mi = 0; mi < 4; mi++) {
        const int row0 = m0 + wm + mi * 16 + g;
#pragma unroll
        for (int ni = 0; ni < 4; ni++) {
            const int colL = wn + ni * 8 + c2;   // within 128-tile
            const float b0 = sBias[colL], b1 = sBias[colL + 1];
            float2 v0 = {acc[mi][ni][0] + b0, acc[mi][ni][1] + b1};
            float2 v1 = {acc[mi][ni][2] + b0, acc[mi][ni][3] + b1};
            *(float2*)(C + (size_t)row0 * N + n0 + colL) = v0;
            *(float2*)(C + (size_t)(row0 + 8) * N + n0 + colL) = v1;
        }
    }
}

// ===========================================================================
// Flash attention (fp32 FFMA) — proven round-2 kernel, unchanged.
// ===========================================================================
__device__ __forceinline__ float warp16_max(float v) {
#pragma unroll
    for (int off = 8; off >= 1; off >>= 1)
        v = fmaxf(v, __shfl_xor_sync(0xffffffffu, v, off));
    return v;
}
__device__ __forceinline__ float warp16_sum(float v) {
#pragma unroll
    for (int off = 8; off >= 1; off >>= 1)
        v += __shfl_xor_sync(0xffffffffu, v, off);
    return v;
}

__global__ __launch_bounds__(256) void flash_attn_kernel(
    const float* __restrict__ qkv, const float* __restrict__ mask,
    float* __restrict__ ctx)
{
    __shared__ float QsT[64][64];
    __shared__ float KP[64][64];
    __shared__ float Vs[64][64];

    const int tid = threadIdx.x;
    const int tx = tid & 15;
    const int ty = tid >> 4;
    const int q0 = blockIdx.x * 64;
    const int h  = blockIdx.y;
    const int b  = blockIdx.z;

    const size_t row_base = (size_t)b * SEQ;
    const int hoff = h * HDIM;

    const int lr = tid & 63;
    const int lc = tid >> 6;

#pragma unroll
    for (int it = 0; it < 4; it++) {
        const int c4 = (lc + it * 4) * 4;
        float4 v = *(const float4*)(qkv + (row_base + q0 + lr) * QKV_N + hoff + c4);
        QsT[c4 + 0][lr] = v.x * 0.125f;
        QsT[c4 + 1][lr] = v.y * 0.125f;
        QsT[c4 + 2][lr] = v.z * 0.125f;
        QsT[c4 + 3][lr] = v.w * 0.125f;
    }

    float mrow[4], lrow[4];
    float4 Oacc[4];
#pragma unroll
    for (int i = 0; i < 4; i++) {
        mrow[i] = -1e30f;
        lrow[i] = 0.0f;
        Oacc[i] = make_float4(0.f, 0.f, 0.f, 0.f);
    }

    for (int k0 = 0; k0 < SEQ; k0 += 64) {
#pragma unroll
        for (int it = 0; it < 4; it++) {
            const int c4 = (lc + it * 4) * 4;
            const size_t kbase = (row_base + k0 + lr) * QKV_N + hoff + c4;
            float4 kv = *(const float4*)(qkv + kbase + HID);
            KP[c4 + 0][lr] = kv.x;
            KP[c4 + 1][lr] = kv.y;
            KP[c4 + 2][lr] = kv.z;
            KP[c4 + 3][lr] = kv.w;

            const int idx = tid + it * 256;
            const int vr = idx >> 4;
            const int vc4 = (idx & 15) * 4;
            *(float4*)&Vs[vr][vc4] =
                *(const float4*)(qkv + (row_base + k0 + vr) * QKV_N + hoff + 2 * HID + vc4);
        }
        __syncthreads();

        float s[4][4];
#pragma unroll
        for (int i = 0; i < 4; i++)
#pragma unroll
            for (int j = 0; j < 4; j++) s[i][j] = 0.0f;

#pragma unroll 8
        for (int d = 0; d < 64; d++) {
            float4 a = *(const float4*)&QsT[d][ty * 4];
            float4 k4 = *(const float4*)&KP[d][tx * 4];
            s[0][0] += a.x * k4.x; s[0][1] += a.x * k4.y; s[0][2] += a.x * k4.z; s[0][3] += a.x * k4.w;
            s[1][0] += a.y * k4.x; s[1][1] += a.y * k4.y; s[1][2] += a.y * k4.z; s[1][3] += a.y * k4.w;
            s[2][0] += a.z * k4.x; s[2][1] += a.z * k4.y; s[2][2] += a.z * k4.z; s[2][3] += a.z * k4.w;
            s[3][0] += a.w * k4.x; s[3][1] += a.w * k4.y; s[3][2] += a.w * k4.z; s[3][3] += a.w * k4.w;
        }

        const float4 mask4 = *(const float4*)(mask + (size_t)b * SEQ + k0 + tx * 4);
#pragma unroll
        for (int i = 0; i < 4; i++) {
            s[i][0] += mask4.x; s[i][1] += mask4.y;
            s[i][2] += mask4.z; s[i][3] += mask4.w;
        }

        float alpha[4], p[4][4];
#pragma unroll
        for (int i = 0; i < 4; i++) {
            float tmax = fmaxf(fmaxf(s[i][0], s[i][1]), fmaxf(s[i][2], s[i][3]));
            tmax = warp16_max(tmax);
            const float newm = fmaxf(mrow[i], tmax);
            alpha[i] = __expf(mrow[i] - newm);
            float rs = 0.0f;
#pragma unroll
            for (int j = 0; j < 4; j++) {
                p[i][j] = __expf(s[i][j] - newm);
                rs += p[i][j];
            }
            rs = warp16_sum(rs);
            lrow[i] = lrow[i] * alpha[i] + rs;
            mrow[i] = newm;
        }
        __syncthreads();

#pragma unroll
        for (int i = 0; i < 4; i++) {
            *(float4*)&KP[ty * 4 + i][tx * 4] = make_float4(p[i][0], p[i][1], p[i][2], p[i][3]);
            Oacc[i].x *= alpha[i]; Oacc[i].y *= alpha[i];
            Oacc[i].z *= alpha[i]; Oacc[i].w *= alpha[i];
        }
        __syncthreads();

#pragma unroll 4
        for (int k4 = 0; k4 < 16; k4++) {
            float4 v0 = *(const float4*)&Vs[k4 * 4 + 0][tx * 4];
            float4 v1 = *(const float4*)&Vs[k4 * 4 + 1][tx * 4];
            float4 v2 = *(const float4*)&Vs[k4 * 4 + 2][tx * 4];
            float4 v3 = *(const float4*)&Vs[k4 * 4 + 3][tx * 4];
#pragma unroll
            for (int i = 0; i < 4; i++) {
                float4 p4 = *(const float4*)&KP[ty * 4 + i][k4 * 4];
                Oacc[i].x += p4.x * v0.x + p4.y * v1.x + p4.z * v2.x + p4.w * v3.x;
                Oacc[i].y += p4.x * v0.y + p4.y * v1.y + p4.z * v2.y + p4.w * v3.y;
                Oacc[i].z += p4.x * v0.z + p4.y * v1.z + p4.z * v2.z + p4.w * v3.z;
                Oacc[i].w += p4.x * v0.w + p4.y * v1.w + p4.z * v2.w + p4.w * v3.w;
            }
        }
        __syncthreads();
    }

#pragma unroll
    for (int i = 0; i < 4; i++) {
        const float inv = 1.0f / lrow[i];
        float4 o = Oacc[i];
        o.x *= inv; o.y *= inv; o.z *= inv; o.w *= inv;
        *(float4*)(ctx + (row_base + q0 + ty * 4 + i) * HID + hoff + tx * 4) = o;
    }
}

// ---------------------------------------------------------------------------
extern "C" void kernel_launch(void* const* d_in, const int* in_sizes, int n_in,
                              void* d_out, int out_size)
{
    const float* hidden = (const float*)d_in[0];
    const float* mask   = (const float*)d_in[1];
    const float* w_attn = (const float*)d_in[2];
    const float* b_attn = (const float*)d_in[3];
    const float* w_proj = (const float*)d_in[4];
    const float* b_proj = (const float*)d_in[5];
    float* out = (float*)d_out;

    float *qkv = nullptr, *ctx = nullptr;
    __nv_bfloat16 *wTh = nullptr, *wTl = nullptr, *pTh = nullptr, *pTl = nullptr;
    cudaGetSymbolAddress((void**)&qkv, g_qkv);
    cudaGetSymbolAddress((void**)&ctx, g_ctx);
    cudaGetSymbolAddress((void**)&wTh, g_wTh);
    cudaGetSymbolAddress((void**)&wTl, g_wTl);
    cudaGetSymbolAddress((void**)&pTh, g_pTh);
    cudaGetSymbolAddress((void**)&pTl, g_pTl);

    // 0) Transpose + split weights to bf16 hi/lo
    transpose_split<<<dim3(QKV_N / 32, HID / 32), dim3(32, 8)>>>(w_attn, wTh, wTl, HID, QKV_N);
    transpose_split<<<dim3(HID / 32, HID / 32), dim3(32, 8)>>>(w_proj, pTh, pTl, HID, HID);

    // 1) QKV = hidden @ c_attn_w + b  (split-bf16 tensor cores)
    gemm_bf16s<<<dim3(QKV_N / 128, M_TOT / 128), 256>>>(
        hidden, wTh, wTl, b_attn, qkv, HID, QKV_N);

    // 2) Flash attention -> ctx [4096, 1024]
    flash_attn_kernel<<<dim3(SEQ / 64, NHEAD, BATCH), 256>>>(qkv, mask, ctx);

    // 3) out = ctx @ c_proj_w + b  (split-bf16 tensor cores)
    gemm_bf16s<<<dim3(HID / 128, M_TOT / 128), 256>>>(
        ctx, pTh, pTl, b_proj, out, HID, HID);
}

// round 5
// speedup vs baseline: 2.6604x; 1.7212x over previous
#include <cuda_runtime.h>
#include <cuda_bf16.h>
#include <cstdint>

// Problem constants
#define BATCH   2
#define SEQ     2048
#define HID     1024
#define NHEAD   16
#define HDIM    64
#define QKV_N   (3 * HID)     // 3072
#define M_TOT   (BATCH * SEQ) // 4096

// Scratch (device globals: allocation-free rule)
__device__ float g_qkv[(size_t)M_TOT * QKV_N]; // [4096, 3072]
__device__ float g_ctx[(size_t)M_TOT * HID];   // [4096, 1024]
__device__ __nv_bfloat16 g_wTh[(size_t)QKV_N * HID];
__device__ __nv_bfloat16 g_wTl[(size_t)QKV_N * HID];
__device__ __nv_bfloat16 g_pTh[(size_t)HID * HID];
__device__ __nv_bfloat16 g_pTl[(size_t)HID * HID];

// ---------------------------------------------------------------------------
// bf16 split helpers
// ---------------------------------------------------------------------------
__device__ __forceinline__ void split_bf16(float a, __nv_bfloat16& h, __nv_bfloat16& l) {
    h = __float2bfloat16_rn(a);
    l = __float2bfloat16_rn(a - __bfloat162float(h));
}

// pack two floats into (hi bf16x2, lo bf16x2)
__device__ __forceinline__ void pack_split(float x, float y, uint32_t& hi, uint32_t& lo) {
    __nv_bfloat16 hx, lx, hy, ly;
    split_bf16(x, hx, lx);
    split_bf16(y, hy, ly);
    __nv_bfloat162 ph = {hx, hy}, pl = {lx, ly};
    hi = *(uint32_t*)&ph;
    lo = *(uint32_t*)&pl;
}

__device__ __forceinline__ void mma_bf16(
    float& d0, float& d1, float& d2, float& d3,
    uint32_t a0, uint32_t a1, uint32_t a2, uint32_t a3,
    uint32_t b0, uint32_t b1)
{
    asm volatile(
        "mma.sync.aligned.m16n8k16.row.col.f32.bf16.bf16.f32 "
        "{%0,%1,%2,%3}, {%4,%5,%6,%7}, {%8,%9}, {%0,%1,%2,%3};"
        : "+f"(d0), "+f"(d1), "+f"(d2), "+f"(d3)
        : "r"(a0), "r"(a1), "r"(a2), "r"(a3), "r"(b0), "r"(b1));
}

// ---------------------------------------------------------------------------
// Prep: transpose + bf16-split weights: B[K][N] -> Bh/Bl [N][K] bf16
// ---------------------------------------------------------------------------
__global__ void transpose_split(const float* __restrict__ B,
                                __nv_bfloat16* __restrict__ Bh,
                                __nv_bfloat16* __restrict__ Bl,
                                int K, int N)
{
    __shared__ float t[32][33];
    const int n0 = blockIdx.x * 32, k0 = blockIdx.y * 32;
    const int x = threadIdx.x, y = threadIdx.y; // (32,8)
#pragma unroll
    for (int i = y; i < 32; i += 8)
        t[i][x] = B[(size_t)(k0 + i) * N + n0 + x];
    __syncthreads();
#pragma unroll
    for (int i = y; i < 32; i += 8) {
        float a = t[x][i];
        __nv_bfloat16 h, l;
        split_bf16(a, h, l);
        Bh[(size_t)(n0 + i) * K + k0 + x] = h;
        Bl[(size_t)(n0 + i) * K + k0 + x] = l;
    }
}

// ---------------------------------------------------------------------------
// Split-bf16 tensor-core GEMM (proven round-4 kernel)
// ---------------------------------------------------------------------------
__global__ __launch_bounds__(256, 2) void gemm_bf16s(
    const float* __restrict__ A,
    const __nv_bfloat16* __restrict__ Bth, const __nv_bfloat16* __restrict__ Btl,
    const float* __restrict__ bias, float* __restrict__ C,
    int K, int N)
{
    __shared__ __nv_bfloat16 sAh[128][40];
    __shared__ __nv_bfloat16 sAl[128][40];
    __shared__ __nv_bfloat16 sBh[128][40];
    __shared__ __nv_bfloat16 sBl[128][40];
    __shared__ float sBias[128];

    const int tid = threadIdx.x;
    const int wid = tid >> 5;
    const int lane = tid & 31;
    const int g  = lane >> 2;
    const int c2 = (lane & 3) * 2;
    const int warp_m = wid & 1;
    const int warp_n = wid >> 1;
    const int m0 = blockIdx.y * 128;
    const int n0 = blockIdx.x * 128;

    if (tid < 128) sBias[tid] = bias[n0 + tid];

    float acc[4][4][4];
#pragma unroll
    for (int mi = 0; mi < 4; mi++)
#pragma unroll
        for (int ni = 0; ni < 4; ni++)
#pragma unroll
            for (int r = 0; r < 4; r++) acc[mi][ni][r] = 0.0f;

    const int wm = warp_m * 64;
    const int wn = warp_n * 32;

    const int nchunks = K >> 5;
    for (int ic = 0; ic < nchunks; ic++) {
        const int k0 = ic << 5;

#pragma unroll
        for (int it = 0; it < 4; it++) {
            const int idx = tid + it * 256;
            const int r = idx >> 3;
            const int q = idx & 7;
            float4 v = *(const float4*)(A + (size_t)(m0 + r) * K + k0 + q * 4);
            uint32_t h0, l0, h1, l1;
            pack_split(v.x, v.y, h0, l0);
            pack_split(v.z, v.w, h1, l1);
            *(uint32_t*)&sAh[r][q * 4 + 0] = h0;
            *(uint32_t*)&sAh[r][q * 4 + 2] = h1;
            *(uint32_t*)&sAl[r][q * 4 + 0] = l0;
            *(uint32_t*)&sAl[r][q * 4 + 2] = l1;
        }
#pragma unroll
        for (int it = 0; it < 4; it++) {
            const int idx = tid + it * 256;
            const int mat = idx >> 9;
            const int j = idx & 511;
            const int r = j >> 2;
            const int q = j & 3;
            const __nv_bfloat16* src = (mat ? Btl : Bth) + (size_t)(n0 + r) * K + k0 + q * 8;
            uint4 v = *(const uint4*)src;
            if (mat) *(uint4*)&sBl[r][q * 8] = v;
            else     *(uint4*)&sBh[r][q * 8] = v;
        }
        __syncthreads();

#pragma unroll
        for (int kk = 0; kk < 32; kk += 16) {
            uint32_t ah[4][4], al[4][4];
#pragma unroll
            for (int mi = 0; mi < 4; mi++) {
                const int R0 = wm + mi * 16 + g;
                const int R1 = R0 + 8;
                ah[mi][0] = *(const uint32_t*)&sAh[R0][kk + c2];
                ah[mi][1] = *(const uint32_t*)&sAh[R1][kk + c2];
                ah[mi][2] = *(const uint32_t*)&sAh[R0][kk + 8 + c2];
                ah[mi][3] = *(const uint32_t*)&sAh[R1][kk + 8 + c2];
                al[mi][0] = *(const uint32_t*)&sAl[R0][kk + c2];
                al[mi][1] = *(const uint32_t*)&sAl[R1][kk + c2];
                al[mi][2] = *(const uint32_t*)&sAl[R0][kk + 8 + c2];
                al[mi][3] = *(const uint32_t*)&sAl[R1][kk + 8 + c2];
            }
#pragma unroll
            for (int ni = 0; ni < 4; ni++) {
                const int nr = wn + ni * 8 + g;
                const uint32_t bh0 = *(const uint32_t*)&sBh[nr][kk + c2];
                const uint32_t bh1 = *(const uint32_t*)&sBh[nr][kk + 8 + c2];
                const uint32_t bl0 = *(const uint32_t*)&sBl[nr][kk + c2];
                const uint32_t bl1 = *(const uint32_t*)&sBl[nr][kk + 8 + c2];
#pragma unroll
                for (int mi = 0; mi < 4; mi++) {
                    mma_bf16(acc[mi][ni][0], acc[mi][ni][1], acc[mi][ni][2], acc[mi][ni][3],
                             ah[mi][0], ah[mi][1], ah[mi][2], ah[mi][3], bh0, bh1);
                    mma_bf16(acc[mi][ni][0], acc[mi][ni][1], acc[mi][ni][2], acc[mi][ni][3],
                             ah[mi][0], ah[mi][1], ah[mi][2], ah[mi][3], bl0, bl1);
                    mma_bf16(acc[mi][ni][0], acc[mi][ni][1], acc[mi][ni][2], acc[mi][ni][3],
                             al[mi][0], al[mi][1], al[mi][2], al[mi][3], bh0, bh1);
                }
            }
        }
        __syncthreads();
    }

#pragma unroll
    for (int mi = 0; mi < 4; mi++) {
        const int row0 = m0 + wm + mi * 16 + g;
#pragma unroll
        for (int ni = 0; ni < 4; ni++) {
            const int colL = wn + ni * 8 + c2;
            const float b0 = sBias[colL], b1 = sBias[colL + 1];
            float2 v0 = {acc[mi][ni][0] + b0, acc[mi][ni][1] + b1};
            float2 v1 = {acc[mi][ni][2] + b0, acc[mi][ni][3] + b1};
            *(float2*)(C + (size_t)row0 * N + n0 + colL) = v0;
            *(float2*)(C + (size_t)(row0 + 8) * N + n0 + colL) = v1;
        }
    }
}

// ===========================================================================
// Flash attention with split-bf16 mma.sync.
// CTA: 128 q rows, 8 warps x 16 rows. Key tiles of 64.
// Q fragments in registers (split hi/lo). K in SMEM [key][d] (B-operand),
// V in SMEM transposed [d][key] (B-operand for PV). P stays in registers:
// score accumulators reinterpret directly as A-fragments.
// ===========================================================================
__global__ __launch_bounds__(256) void flash_attn_tc(
    const float* __restrict__ qkv, const float* __restrict__ mask,
    float* __restrict__ ctx)
{
    __shared__ __nv_bfloat16 sKh[64][72];
    __shared__ __nv_bfloat16 sKl[64][72];
    __shared__ __nv_bfloat16 sVTh[64][72];
    __shared__ __nv_bfloat16 sVTl[64][72];
    __shared__ float sMask[64];

    const int tid  = threadIdx.x;
    const int wid  = tid >> 5;
    const int lane = tid & 31;
    const int g    = lane >> 2;        // 0..7
    const int c2   = (lane & 3) * 2;   // 0,2,4,6
    const int q0   = blockIdx.x * 128;
    const int h    = blockIdx.y;
    const int b    = blockIdx.z;

    const size_t row_base = (size_t)b * SEQ;
    const int hoff = h * HDIM;

    // ---- Q fragments (rows q0 + wid*16 + g, +8), scaled 0.125, split ----
    uint32_t qh[4][4], ql[4][4];
    {
        const float* qr0 = qkv + (row_base + q0 + wid * 16 + g) * QKV_N + hoff;
        const float* qr1 = qr0 + 8 * QKV_N;
#pragma unroll
        for (int s = 0; s < 4; s++) {
            float2 f0 = *(const float2*)(qr0 + s * 16 + c2);
            float2 f1 = *(const float2*)(qr1 + s * 16 + c2);
            float2 f2 = *(const float2*)(qr0 + s * 16 + 8 + c2);
            float2 f3 = *(const float2*)(qr1 + s * 16 + 8 + c2);
            pack_split(f0.x * 0.125f, f0.y * 0.125f, qh[s][0], ql[s][0]);
            pack_split(f1.x * 0.125f, f1.y * 0.125f, qh[s][1], ql[s][1]);
            pack_split(f2.x * 0.125f, f2.y * 0.125f, qh[s][2], ql[s][2]);
            pack_split(f3.x * 0.125f, f3.y * 0.125f, qh[s][3], ql[s][3]);
        }
    }

    float o[8][4];
#pragma unroll
    for (int j = 0; j < 8; j++)
#pragma unroll
        for (int r = 0; r < 4; r++) o[j][r] = 0.0f;
    float m0 = -1e30f, m1 = -1e30f, l0 = 0.0f, l1 = 0.0f;

    for (int k0 = 0; k0 < SEQ; k0 += 64) {
        // ---- Load K tile -> split SMEM [key][d] ----
#pragma unroll
        for (int it = 0; it < 4; it++) {
            const int idx = tid + it * 256;   // 0..1023
            const int r = idx >> 4;           // key 0..63
            const int q = idx & 15;           // float4 col
            float4 v = *(const float4*)(qkv + (row_base + k0 + r) * QKV_N + hoff + HID + q * 4);
            uint32_t h0, lo0, h1, lo1;
            pack_split(v.x, v.y, h0, lo0);
            pack_split(v.z, v.w, h1, lo1);
            *(uint32_t*)&sKh[r][q * 4 + 0] = h0;
            *(uint32_t*)&sKh[r][q * 4 + 2] = h1;
            *(uint32_t*)&sKl[r][q * 4 + 0] = lo0;
            *(uint32_t*)&sKl[r][q * 4 + 2] = lo1;
        }
        // ---- Load V tile -> split transposed SMEM [d][key] ----
#pragma unroll
        for (int it = 0; it < 2; it++) {
            const int idx = tid + it * 256;   // 0..511
            const int kp = idx & 31;          // key pair
            const int d4 = idx >> 5;          // 0..15
            const float* v0p = qkv + (row_base + k0 + 2 * kp) * QKV_N + hoff + 2 * HID + d4 * 4;
            float4 a = *(const float4*)v0p;
            float4 bb = *(const float4*)(v0p + QKV_N);
            const float av[4] = {a.x, a.y, a.z, a.w};
            const float bv[4] = {bb.x, bb.y, bb.z, bb.w};
#pragma unroll
            for (int i = 0; i < 4; i++) {
                uint32_t hi, lo;
                pack_split(av[i], bv[i], hi, lo);
                *(uint32_t*)&sVTh[d4 * 4 + i][2 * kp] = hi;
                *(uint32_t*)&sVTl[d4 * 4 + i][2 * kp] = lo;
            }
        }
        if (tid < 64) sMask[tid] = mask[(size_t)b * SEQ + k0 + tid];
        __syncthreads();

        // ---- S = Q K^T (split, 3 passes) ----
        float sc[8][4];
#pragma unroll
        for (int j = 0; j < 8; j++)
#pragma unroll
            for (int r = 0; r < 4; r++) sc[j][r] = 0.0f;

#pragma unroll
        for (int j = 0; j < 8; j++) {
            const int nr = j * 8 + g;
#pragma unroll
            for (int s = 0; s < 4; s++) {
                const uint32_t bh0 = *(const uint32_t*)&sKh[nr][s * 16 + c2];
                const uint32_t bh1 = *(const uint32_t*)&sKh[nr][s * 16 + 8 + c2];
                const uint32_t bl0 = *(const uint32_t*)&sKl[nr][s * 16 + c2];
                const uint32_t bl1 = *(const uint32_t*)&sKl[nr][s * 16 + 8 + c2];
                mma_bf16(sc[j][0], sc[j][1], sc[j][2], sc[j][3],
                         qh[s][0], qh[s][1], qh[s][2], qh[s][3], bh0, bh1);
                mma_bf16(sc[j][0], sc[j][1], sc[j][2], sc[j][3],
                         qh[s][0], qh[s][1], qh[s][2], qh[s][3], bl0, bl1);
                mma_bf16(sc[j][0], sc[j][1], sc[j][2], sc[j][3],
                         ql[s][0], ql[s][1], ql[s][2], ql[s][3], bh0, bh1);
            }
        }

        // ---- mask + online softmax ----
        float rmax0 = -1e30f, rmax1 = -1e30f;
#pragma unroll
        for (int j = 0; j < 8; j++) {
            const float mv0 = sMask[j * 8 + c2];
            const float mv1 = sMask[j * 8 + c2 + 1];
            sc[j][0] += mv0; sc[j][1] += mv1;
            sc[j][2] += mv0; sc[j][3] += mv1;
            rmax0 = fmaxf(rmax0, fmaxf(sc[j][0], sc[j][1]));
            rmax1 = fmaxf(rmax1, fmaxf(sc[j][2], sc[j][3]));
        }
#pragma unroll
        for (int off = 1; off <= 2; off <<= 1) {
            rmax0 = fmaxf(rmax0, __shfl_xor_sync(0xffffffffu, rmax0, off));
            rmax1 = fmaxf(rmax1, __shfl_xor_sync(0xffffffffu, rmax1, off));
        }
        const float nm0 = fmaxf(m0, rmax0);
        const float nm1 = fmaxf(m1, rmax1);
        const float a0 = __expf(m0 - nm0);
        const float a1 = __expf(m1 - nm1);

        float rs0 = 0.0f, rs1 = 0.0f;
#pragma unroll
        for (int j = 0; j < 8; j++) {
            sc[j][0] = __expf(sc[j][0] - nm0);
            sc[j][1] = __expf(sc[j][1] - nm0);
            sc[j][2] = __expf(sc[j][2] - nm1);
            sc[j][3] = __expf(sc[j][3] - nm1);
            rs0 += sc[j][0] + sc[j][1];
            rs1 += sc[j][2] + sc[j][3];
        }
#pragma unroll
        for (int off = 1; off <= 2; off <<= 1) {
            rs0 += __shfl_xor_sync(0xffffffffu, rs0, off);
            rs1 += __shfl_xor_sync(0xffffffffu, rs1, off);
        }
        l0 = l0 * a0 + rs0;
        l1 = l1 * a1 + rs1;
        m0 = nm0;
        m1 = nm1;
#pragma unroll
        for (int j = 0; j < 8; j++) {
            o[j][0] *= a0; o[j][1] *= a0;
            o[j][2] *= a1; o[j][3] *= a1;
        }

        // ---- pack P -> A-fragments (split) ----
        uint32_t ph[4][4], pl[4][4];
#pragma unroll
        for (int s = 0; s < 4; s++) {
            pack_split(sc[2 * s][0],     sc[2 * s][1],     ph[s][0], pl[s][0]);
            pack_split(sc[2 * s][2],     sc[2 * s][3],     ph[s][1], pl[s][1]);
            pack_split(sc[2 * s + 1][0], sc[2 * s + 1][1], ph[s][2], pl[s][2]);
            pack_split(sc[2 * s + 1][2], sc[2 * s + 1][3], ph[s][3], pl[s][3]);
        }

        // ---- O += P V (split, 3 passes) ----
#pragma unroll
        for (int j = 0; j < 8; j++) {
            const int nr = j * 8 + g;
#pragma unroll
            for (int s = 0; s < 4; s++) {
                const uint32_t bh0 = *(const uint32_t*)&sVTh[nr][s * 16 + c2];
                const uint32_t bh1 = *(const uint32_t*)&sVTh[nr][s * 16 + 8 + c2];
                const uint32_t bl0 = *(const uint32_t*)&sVTl[nr][s * 16 + c2];
                const uint32_t bl1 = *(const uint32_t*)&sVTl[nr][s * 16 + 8 + c2];
                mma_bf16(o[j][0], o[j][1], o[j][2], o[j][3],
                         ph[s][0], ph[s][1], ph[s][2], ph[s][3], bh0, bh1);
                mma_bf16(o[j][0], o[j][1], o[j][2], o[j][3],
                         ph[s][0], ph[s][1], ph[s][2], ph[s][3], bl0, bl1);
                mma_bf16(o[j][0], o[j][1], o[j][2], o[j][3],
                         pl[s][0], pl[s][1], pl[s][2], pl[s][3], bh0, bh1);
            }
        }
        __syncthreads();
    }

    // ---- finalize + store ctx[b, s, hoff + d] ----
    const float inv0 = 1.0f / l0;
    const float inv1 = 1.0f / l1;
    const size_t r0 = row_base + q0 + wid * 16 + g;
    const size_t r1 = r0 + 8;
#pragma unroll
    for (int j = 0; j < 8; j++) {
        float2 v0 = {o[j][0] * inv0, o[j][1] * inv0};
        float2 v1 = {o[j][2] * inv1, o[j][3] * inv1};
        *(float2*)(ctx + r0 * HID + hoff + j * 8 + c2) = v0;
        *(float2*)(ctx + r1 * HID + hoff + j * 8 + c2) = v1;
    }
}

// ---------------------------------------------------------------------------
extern "C" void kernel_launch(void* const* d_in, const int* in_sizes, int n_in,
                              void* d_out, int out_size)
{
    const float* hidden = (const float*)d_in[0];
    const float* mask   = (const float*)d_in[1];
    const float* w_attn = (const float*)d_in[2];
    const float* b_attn = (const float*)d_in[3];
    const float* w_proj = (const float*)d_in[4];
    const float* b_proj = (const float*)d_in[5];
    float* out = (float*)d_out;

    float *qkv = nullptr, *ctx = nullptr;
    __nv_bfloat16 *wTh = nullptr, *wTl = nullptr, *pTh = nullptr, *pTl = nullptr;
    cudaGetSymbolAddress((void**)&qkv, g_qkv);
    cudaGetSymbolAddress((void**)&ctx, g_ctx);
    cudaGetSymbolAddress((void**)&wTh, g_wTh);
    cudaGetSymbolAddress((void**)&wTl, g_wTl);
    cudaGetSymbolAddress((void**)&pTh, g_pTh);
    cudaGetSymbolAddress((void**)&pTl, g_pTl);

    // 0) Transpose + split weights to bf16 hi/lo
    transpose_split<<<dim3(QKV_N / 32, HID / 32), dim3(32, 8)>>>(w_attn, wTh, wTl, HID, QKV_N);
    transpose_split<<<dim3(HID / 32, HID / 32), dim3(32, 8)>>>(w_proj, pTh, pTl, HID, HID);

    // 1) QKV = hidden @ c_attn_w + b  (split-bf16 tensor cores)
    gemm_bf16s<<<dim3(QKV_N / 128, M_TOT / 128), 256>>>(
        hidden, wTh, wTl, b_attn, qkv, HID, QKV_N);

    // 2) Flash attention (split-bf16 tensor cores) -> ctx [4096, 1024]
    flash_attn_tc<<<dim3(SEQ / 128, NHEAD, BATCH), 256>>>(qkv, mask, ctx);

    // 3) out = ctx @ c_proj_w + b  (split-bf16 tensor cores)
    gemm_bf16s<<<dim3(HID / 128, M_TOT / 128), 256>>>(
        ctx, pTh, pTl, b_proj, out, HID, HID);
}

// round 6
// speedup vs baseline: 2.8334x; 1.0650x over previous
#include <cuda_runtime.h>
#include <cuda_bf16.h>
#include <cstdint>

// Problem constants
#define BATCH   2
#define SEQ     2048
#define HID     1024
#define NHEAD   16
#define HDIM    64
#define QKV_N   (3 * HID)     // 3072
#define M_TOT   (BATCH * SEQ) // 4096

// Scratch (device globals: allocation-free rule)
__device__ float g_ctx[(size_t)M_TOT * HID];                  // [4096, 1024]
__device__ __nv_bfloat16 g_qkvh[(size_t)M_TOT * QKV_N];       // qkv split hi
__device__ __nv_bfloat16 g_qkvl[(size_t)M_TOT * QKV_N];       // qkv split lo
__device__ __nv_bfloat16 g_vTh[(size_t)BATCH * HID * SEQ];    // V^T hi [b][h*64+d][key]
__device__ __nv_bfloat16 g_vTl[(size_t)BATCH * HID * SEQ];    // V^T lo
__device__ __nv_bfloat16 g_wTh[(size_t)QKV_N * HID];
__device__ __nv_bfloat16 g_wTl[(size_t)QKV_N * HID];
__device__ __nv_bfloat16 g_pTh[(size_t)HID * HID];
__device__ __nv_bfloat16 g_pTl[(size_t)HID * HID];

// ---------------------------------------------------------------------------
// Helpers
// ---------------------------------------------------------------------------
__device__ __forceinline__ void split_bf16(float a, __nv_bfloat16& h, __nv_bfloat16& l) {
    h = __float2bfloat16_rn(a);
    l = __float2bfloat16_rn(a - __bfloat162float(h));
}

__device__ __forceinline__ void pack_split(float x, float y, uint32_t& hi, uint32_t& lo) {
    __nv_bfloat16 hx, lx, hy, ly;
    split_bf16(x, hx, lx);
    split_bf16(y, hy, ly);
    __nv_bfloat162 ph = {hx, hy}, pl = {lx, ly};
    hi = *(uint32_t*)&ph;
    lo = *(uint32_t*)&pl;
}

__device__ __forceinline__ void mma_bf16(
    float& d0, float& d1, float& d2, float& d3,
    uint32_t a0, uint32_t a1, uint32_t a2, uint32_t a3,
    uint32_t b0, uint32_t b1)
{
    asm volatile(
        "mma.sync.aligned.m16n8k16.row.col.f32.bf16.bf16.f32 "
        "{%0,%1,%2,%3}, {%4,%5,%6,%7}, {%8,%9}, {%0,%1,%2,%3};"
        : "+f"(d0), "+f"(d1), "+f"(d2), "+f"(d3)
        : "r"(a0), "r"(a1), "r"(a2), "r"(a3), "r"(b0), "r"(b1));
}

__device__ __forceinline__ uint32_t smem_u32(const void* p) {
    uint32_t a;
    asm("{ .reg .u64 t; cvta.to.shared.u64 t, %1; cvt.u32.u64 %0, t; }"
        : "=r"(a) : "l"(p));
    return a;
}

__device__ __forceinline__ void cp_async16(uint32_t dst, const void* src) {
    asm volatile("cp.async.ca.shared.global [%0], [%1], 16;" :: "r"(dst), "l"(src));
}
#define CP_COMMIT() asm volatile("cp.async.commit_group;" ::: "memory")
#define CP_WAIT(n)  asm volatile("cp.async.wait_group %0;" :: "n"(n) : "memory")

// ---------------------------------------------------------------------------
// Prep: transpose + bf16-split weights: B[K][N] -> Bh/Bl [N][K] bf16
// ---------------------------------------------------------------------------
__global__ void transpose_split(const float* __restrict__ B,
                                __nv_bfloat16* __restrict__ Bh,
                                __nv_bfloat16* __restrict__ Bl,
                                int K, int N)
{
    __shared__ float t[32][33];
    const int n0 = blockIdx.x * 32, k0 = blockIdx.y * 32;
    const int x = threadIdx.x, y = threadIdx.y; // (32,8)
#pragma unroll
    for (int i = y; i < 32; i += 8)
        t[i][x] = B[(size_t)(k0 + i) * N + n0 + x];
    __syncthreads();
#pragma unroll
    for (int i = y; i < 32; i += 8) {
        float a = t[x][i];
        __nv_bfloat16 h, l;
        split_bf16(a, h, l);
        Bh[(size_t)(n0 + i) * K + k0 + x] = h;
        Bl[(size_t)(n0 + i) * K + k0 + x] = l;
    }
}

// ---------------------------------------------------------------------------
// Transpose V region of split qkv into [b][h*64+d][key] (bf16 hi/lo)
// ---------------------------------------------------------------------------
__global__ void transpose_v(const __nv_bfloat16* __restrict__ qh,
                            const __nv_bfloat16* __restrict__ ql,
                            __nv_bfloat16* __restrict__ vTh,
                            __nv_bfloat16* __restrict__ vTl)
{
    __shared__ __nv_bfloat16 th[32][34];
    __shared__ __nv_bfloat16 tl[32][34];
    const int b  = blockIdx.z;
    const int k0 = blockIdx.x * 32;   // key
    const int d0 = blockIdx.y * 32;   // dim (h*64+d)
    const int x = threadIdx.x, y = threadIdx.y; // (32,8)
#pragma unroll
    for (int i = y; i < 32; i += 8) {
        const size_t src = (size_t)(b * SEQ + k0 + i) * QKV_N + 2 * HID + d0 + x;
        th[i][x] = qh[src];
        tl[i][x] = ql[src];
    }
    __syncthreads();
#pragma unroll
    for (int i = y; i < 32; i += 8) {
        const size_t dst = ((size_t)b * HID + d0 + i) * SEQ + k0 + x;
        vTh[dst] = th[x][i];
        vTl[dst] = tl[x][i];
    }
}

// ---------------------------------------------------------------------------
// Split-bf16 tensor-core GEMM. Output: fp32 C (if Ch==nullptr) or split bf16.
// ---------------------------------------------------------------------------
__global__ __launch_bounds__(256, 2) void gemm_bf16s(
    const float* __restrict__ A,
    const __nv_bfloat16* __restrict__ Bth, const __nv_bfloat16* __restrict__ Btl,
    const float* __restrict__ bias, float* __restrict__ C,
    __nv_bfloat16* __restrict__ Ch, __nv_bfloat16* __restrict__ Cl,
    int K, int N)
{
    __shared__ __nv_bfloat16 sAh[128][40];
    __shared__ __nv_bfloat16 sAl[128][40];
    __shared__ __nv_bfloat16 sBh[128][40];
    __shared__ __nv_bfloat16 sBl[128][40];
    __shared__ float sBias[128];

    const int tid = threadIdx.x;
    const int wid = tid >> 5;
    const int lane = tid & 31;
    const int g  = lane >> 2;
    const int c2 = (lane & 3) * 2;
    const int warp_m = wid & 1;
    const int warp_n = wid >> 1;
    const int m0 = blockIdx.y * 128;
    const int n0 = blockIdx.x * 128;

    if (tid < 128) sBias[tid] = bias[n0 + tid];

    float acc[4][4][4];
#pragma unroll
    for (int mi = 0; mi < 4; mi++)
#pragma unroll
        for (int ni = 0; ni < 4; ni++)
#pragma unroll
            for (int r = 0; r < 4; r++) acc[mi][ni][r] = 0.0f;

    const int wm = warp_m * 64;
    const int wn = warp_n * 32;

    const int nchunks = K >> 5;
    for (int ic = 0; ic < nchunks; ic++) {
        const int k0 = ic << 5;

#pragma unroll
        for (int it = 0; it < 4; it++) {
            const int idx = tid + it * 256;
            const int r = idx >> 3;
            const int q = idx & 7;
            float4 v = *(const float4*)(A + (size_t)(m0 + r) * K + k0 + q * 4);
            uint32_t h0, l0, h1, l1;
            pack_split(v.x, v.y, h0, l0);
            pack_split(v.z, v.w, h1, l1);
            *(uint32_t*)&sAh[r][q * 4 + 0] = h0;
            *(uint32_t*)&sAh[r][q * 4 + 2] = h1;
            *(uint32_t*)&sAl[r][q * 4 + 0] = l0;
            *(uint32_t*)&sAl[r][q * 4 + 2] = l1;
        }
#pragma unroll
        for (int it = 0; it < 4; it++) {
            const int idx = tid + it * 256;
            const int mat = idx >> 9;
            const int j = idx & 511;
            const int r = j >> 2;
            const int q = j & 3;
            const __nv_bfloat16* src = (mat ? Btl : Bth) + (size_t)(n0 + r) * K + k0 + q * 8;
            uint4 v = *(const uint4*)src;
            if (mat) *(uint4*)&sBl[r][q * 8] = v;
            else     *(uint4*)&sBh[r][q * 8] = v;
        }
        __syncthreads();

#pragma unroll
        for (int kk = 0; kk < 32; kk += 16) {
            uint32_t ah[4][4], al[4][4];
#pragma unroll
            for (int mi = 0; mi < 4; mi++) {
                const int R0 = wm + mi * 16 + g;
                const int R1 = R0 + 8;
                ah[mi][0] = *(const uint32_t*)&sAh[R0][kk + c2];
                ah[mi][1] = *(const uint32_t*)&sAh[R1][kk + c2];
                ah[mi][2] = *(const uint32_t*)&sAh[R0][kk + 8 + c2];
                ah[mi][3] = *(const uint32_t*)&sAh[R1][kk + 8 + c2];
                al[mi][0] = *(const uint32_t*)&sAl[R0][kk + c2];
                al[mi][1] = *(const uint32_t*)&sAl[R1][kk + c2];
                al[mi][2] = *(const uint32_t*)&sAl[R0][kk + 8 + c2];
                al[mi][3] = *(const uint32_t*)&sAl[R1][kk + 8 + c2];
            }
#pragma unroll
            for (int ni = 0; ni < 4; ni++) {
                const int nr = wn + ni * 8 + g;
                const uint32_t bh0 = *(const uint32_t*)&sBh[nr][kk + c2];
                const uint32_t bh1 = *(const uint32_t*)&sBh[nr][kk + 8 + c2];
                const uint32_t bl0 = *(const uint32_t*)&sBl[nr][kk + c2];
                const uint32_t bl1 = *(const uint32_t*)&sBl[nr][kk + 8 + c2];
#pragma unroll
                for (int mi = 0; mi < 4; mi++) {
                    mma_bf16(acc[mi][ni][0], acc[mi][ni][1], acc[mi][ni][2], acc[mi][ni][3],
                             ah[mi][0], ah[mi][1], ah[mi][2], ah[mi][3], bh0, bh1);
                    mma_bf16(acc[mi][ni][0], acc[mi][ni][1], acc[mi][ni][2], acc[mi][ni][3],
                             ah[mi][0], ah[mi][1], ah[mi][2], ah[mi][3], bl0, bl1);
                    mma_bf16(acc[mi][ni][0], acc[mi][ni][1], acc[mi][ni][2], acc[mi][ni][3],
                             al[mi][0], al[mi][1], al[mi][2], al[mi][3], bh0, bh1);
                }
            }
        }
        __syncthreads();
    }

    if (Ch) {
        // split-bf16 output
#pragma unroll
        for (int mi = 0; mi < 4; mi++) {
            const int row0 = m0 + wm + mi * 16 + g;
#pragma unroll
            for (int ni = 0; ni < 4; ni++) {
                const int colL = wn + ni * 8 + c2;
                const float b0 = sBias[colL], b1 = sBias[colL + 1];
                uint32_t h0, l0, h1, l1;
                pack_split(acc[mi][ni][0] + b0, acc[mi][ni][1] + b1, h0, l0);
                pack_split(acc[mi][ni][2] + b0, acc[mi][ni][3] + b1, h1, l1);
                const size_t o0 = (size_t)row0 * N + n0 + colL;
                const size_t o1 = (size_t)(row0 + 8) * N + n0 + colL;
                *(uint32_t*)(Ch + o0) = h0;
                *(uint32_t*)(Cl + o0) = l0;
                *(uint32_t*)(Ch + o1) = h1;
                *(uint32_t*)(Cl + o1) = l1;
            }
        }
    } else {
#pragma unroll
        for (int mi = 0; mi < 4; mi++) {
            const int row0 = m0 + wm + mi * 16 + g;
#pragma unroll
            for (int ni = 0; ni < 4; ni++) {
                const int colL = wn + ni * 8 + c2;
                const float b0 = sBias[colL], b1 = sBias[colL + 1];
                float2 v0 = {acc[mi][ni][0] + b0, acc[mi][ni][1] + b1};
                float2 v1 = {acc[mi][ni][2] + b0, acc[mi][ni][3] + b1};
                *(float2*)(C + (size_t)row0 * N + n0 + colL) = v0;
                *(float2*)(C + (size_t)(row0 + 8) * N + n0 + colL) = v1;
            }
        }
    }
}

// ===========================================================================
// Flash attention, split-bf16 mma + cp.async double-buffered K/V tiles.
// Dynamic SMEM layout per stage (36864B): Kh[64][72] Kl Vh[64][72] Vl.
// Mask floats at offset 73728 (+256 per stage). Total 74240B.
// ===========================================================================
#define KH_OFF   0
#define KL_OFF   9216
#define VH_OFF   18432
#define VL_OFF   27648
#define STAGE_SZ 36864
#define MASK_OFF 73728
#define SMEM_TOT 74240

__global__ __launch_bounds__(256, 2) void flash_attn_tc(
    const __nv_bfloat16* __restrict__ qkvh, const __nv_bfloat16* __restrict__ qkvl,
    const __nv_bfloat16* __restrict__ vTh,  const __nv_bfloat16* __restrict__ vTl,
    const float* __restrict__ mask, float* __restrict__ ctx)
{
    extern __shared__ char smem[];
    const uint32_t smem_base = smem_u32(smem);

    const int tid  = threadIdx.x;
    const int wid  = tid >> 5;
    const int lane = tid & 31;
    const int g    = lane >> 2;        // 0..7
    const int c2   = (lane & 3) * 2;   // 0,2,4,6
    const int q0   = blockIdx.x * 128;
    const int h    = blockIdx.y;
    const int b    = blockIdx.z;

    const size_t row_base = (size_t)b * SEQ;
    const int hoff  = h * HDIM;
    const int khoff = HID + hoff;
    const size_t vrow_base = ((size_t)b * HID + hoff) * SEQ;

    // ---- Q fragments: direct bf16 loads (scale folded into scores) ----
    uint32_t qh[4][4], ql[4][4];
    {
        const __nv_bfloat16* qr0 = qkvh + (row_base + q0 + wid * 16 + g) * QKV_N + hoff;
        const __nv_bfloat16* qr1 = qr0 + 8 * QKV_N;
        const __nv_bfloat16* lr0 = qkvl + (row_base + q0 + wid * 16 + g) * QKV_N + hoff;
        const __nv_bfloat16* lr1 = lr0 + 8 * QKV_N;
#pragma unroll
        for (int s = 0; s < 4; s++) {
            qh[s][0] = *(const uint32_t*)(qr0 + s * 16 + c2);
            qh[s][1] = *(const uint32_t*)(qr1 + s * 16 + c2);
            qh[s][2] = *(const uint32_t*)(qr0 + s * 16 + 8 + c2);
            qh[s][3] = *(const uint32_t*)(qr1 + s * 16 + 8 + c2);
            ql[s][0] = *(const uint32_t*)(lr0 + s * 16 + c2);
            ql[s][1] = *(const uint32_t*)(lr1 + s * 16 + c2);
            ql[s][2] = *(const uint32_t*)(lr0 + s * 16 + 8 + c2);
            ql[s][3] = *(const uint32_t*)(lr1 + s * 16 + 8 + c2);
        }
    }

    float o[8][4];
#pragma unroll
    for (int j = 0; j < 8; j++)
#pragma unroll
        for (int r = 0; r < 4; r++) o[j][r] = 0.0f;
    float m0 = -1e30f, m1 = -1e30f, l0 = 0.0f, l1 = 0.0f;

    // ---- tile load issue (cp.async) ----
    auto issue_tile = [&](int k0, int st) {
        const uint32_t sb = smem_base + st * STAGE_SZ;
#pragma unroll
        for (int it = 0; it < 4; it++) {         // K: 1024 x 16B chunks
            const int idx = tid + it * 256;
            const int bufsel = idx >> 9;
            const int j = idx & 511;
            const int r = j >> 3;
            const int q = j & 7;
            const __nv_bfloat16* src =
                (bufsel ? qkvl : qkvh) + (row_base + k0 + r) * QKV_N + khoff + q * 8;
            cp_async16(sb + (bufsel ? KL_OFF : KH_OFF) + r * 144 + q * 16, src);
        }
#pragma unroll
        for (int it = 0; it < 4; it++) {         // V^T: 1024 x 16B chunks
            const int idx = tid + it * 256;
            const int bufsel = idx >> 9;
            const int j = idx & 511;
            const int r = j >> 3;                 // dim
            const int q = j & 7;
            const __nv_bfloat16* src =
                (bufsel ? vTl : vTh) + vrow_base + (size_t)r * SEQ + k0 + q * 8;
            cp_async16(sb + (bufsel ? VL_OFF : VH_OFF) + r * 144 + q * 16, src);
        }
        if (tid < 64)
            *(float*)(smem + MASK_OFF + st * 256 + tid * 4) = mask[(size_t)b * SEQ + k0 + tid];
        CP_COMMIT();
    };

    issue_tile(0, 0);

    for (int i = 0; i < SEQ / 64; i++) {
        const int st = i & 1;
        if (i < SEQ / 64 - 1) {
            issue_tile((i + 1) * 64, st ^ 1);
            CP_WAIT(1);
        } else {
            CP_WAIT(0);
        }
        __syncthreads();

        const __nv_bfloat16* Kh = (const __nv_bfloat16*)(smem + st * STAGE_SZ + KH_OFF);
        const __nv_bfloat16* Kl = (const __nv_bfloat16*)(smem + st * STAGE_SZ + KL_OFF);
        const __nv_bfloat16* Vh = (const __nv_bfloat16*)(smem + st * STAGE_SZ + VH_OFF);
        const __nv_bfloat16* Vl = (const __nv_bfloat16*)(smem + st * STAGE_SZ + VL_OFF);
        const float* sMask = (const float*)(smem + MASK_OFF + st * 256);

        // ---- S = Q K^T (split, 3 passes) ----
        float sc[8][4];
#pragma unroll
        for (int j = 0; j < 8; j++)
#pragma unroll
            for (int r = 0; r < 4; r++) sc[j][r] = 0.0f;

#pragma unroll
        for (int j = 0; j < 8; j++) {
            const int nr = j * 8 + g;
#pragma unroll
            for (int s = 0; s < 4; s++) {
                const uint32_t bh0 = *(const uint32_t*)(Kh + nr * 72 + s * 16 + c2);
                const uint32_t bh1 = *(const uint32_t*)(Kh + nr * 72 + s * 16 + 8 + c2);
                const uint32_t bl0 = *(const uint32_t*)(Kl + nr * 72 + s * 16 + c2);
                const uint32_t bl1 = *(const uint32_t*)(Kl + nr * 72 + s * 16 + 8 + c2);
                mma_bf16(sc[j][0], sc[j][1], sc[j][2], sc[j][3],
                         qh[s][0], qh[s][1], qh[s][2], qh[s][3], bh0, bh1);
                mma_bf16(sc[j][0], sc[j][1], sc[j][2], sc[j][3],
                         qh[s][0], qh[s][1], qh[s][2], qh[s][3], bl0, bl1);
                mma_bf16(sc[j][0], sc[j][1], sc[j][2], sc[j][3],
                         ql[s][0], ql[s][1], ql[s][2], ql[s][3], bh0, bh1);
            }
        }

        // ---- scale + mask + online softmax ----
        float rmax0 = -1e30f, rmax1 = -1e30f;
#pragma unroll
        for (int j = 0; j < 8; j++) {
            const float mv0 = sMask[j * 8 + c2];
            const float mv1 = sMask[j * 8 + c2 + 1];
            sc[j][0] = sc[j][0] * 0.125f + mv0;
            sc[j][1] = sc[j][1] * 0.125f + mv1;
            sc[j][2] = sc[j][2] * 0.125f + mv0;
            sc[j][3] = sc[j][3] * 0.125f + mv1;
            rmax0 = fmaxf(rmax0, fmaxf(sc[j][0], sc[j][1]));
            rmax1 = fmaxf(rmax1, fmaxf(sc[j][2], sc[j][3]));
        }
#pragma unroll
        for (int off = 1; off <= 2; off <<= 1) {
            rmax0 = fmaxf(rmax0, __shfl_xor_sync(0xffffffffu, rmax0, off));
            rmax1 = fmaxf(rmax1, __shfl_xor_sync(0xffffffffu, rmax1, off));
        }
        const float nm0 = fmaxf(m0, rmax0);
        const float nm1 = fmaxf(m1, rmax1);
        const float a0 = __expf(m0 - nm0);
        const float a1 = __expf(m1 - nm1);

        float rs0 = 0.0f, rs1 = 0.0f;
#pragma unroll
        for (int j = 0; j < 8; j++) {
            sc[j][0] = __expf(sc[j][0] - nm0);
            sc[j][1] = __expf(sc[j][1] - nm0);
            sc[j][2] = __expf(sc[j][2] - nm1);
            sc[j][3] = __expf(sc[j][3] - nm1);
            rs0 += sc[j][0] + sc[j][1];
            rs1 += sc[j][2] + sc[j][3];
        }
#pragma unroll
        for (int off = 1; off <= 2; off <<= 1) {
            rs0 += __shfl_xor_sync(0xffffffffu, rs0, off);
            rs1 += __shfl_xor_sync(0xffffffffu, rs1, off);
        }
        l0 = l0 * a0 + rs0;
        l1 = l1 * a1 + rs1;
        m0 = nm0;
        m1 = nm1;
#pragma unroll
        for (int j = 0; j < 8; j++) {
            o[j][0] *= a0; o[j][1] *= a0;
            o[j][2] *= a1; o[j][3] *= a1;
        }

        // ---- pack P -> A fragments (split) ----
        uint32_t ph[4][4], pl[4][4];
#pragma unroll
        for (int s = 0; s < 4; s++) {
            pack_split(sc[2 * s][0],     sc[2 * s][1],     ph[s][0], pl[s][0]);
            pack_split(sc[2 * s][2],     sc[2 * s][3],     ph[s][1], pl[s][1]);
            pack_split(sc[2 * s + 1][0], sc[2 * s + 1][1], ph[s][2], pl[s][2]);
            pack_split(sc[2 * s + 1][2], sc[2 * s + 1][3], ph[s][3], pl[s][3]);
        }

        // ---- O += P V (split, 3 passes) ----
#pragma unroll
        for (int j = 0; j < 8; j++) {
            const int nr = j * 8 + g;
#pragma unroll
            for (int s = 0; s < 4; s++) {
                const uint32_t bh0 = *(const uint32_t*)(Vh + nr * 72 + s * 16 + c2);
                const uint32_t bh1 = *(const uint32_t*)(Vh + nr * 72 + s * 16 + 8 + c2);
                const uint32_t bl0 = *(const uint32_t*)(Vl + nr * 72 + s * 16 + c2);
                const uint32_t bl1 = *(const uint32_t*)(Vl + nr * 72 + s * 16 + 8 + c2);
                mma_bf16(o[j][0], o[j][1], o[j][2], o[j][3],
                         ph[s][0], ph[s][1], ph[s][2], ph[s][3], bh0, bh1);
                mma_bf16(o[j][0], o[j][1], o[j][2], o[j][3],
                         ph[s][0], ph[s][1], ph[s][2], ph[s][3], bl0, bl1);
                mma_bf16(o[j][0], o[j][1], o[j][2], o[j][3],
                         pl[s][0], pl[s][1], pl[s][2], pl[s][3], bh0, bh1);
            }
        }
        __syncthreads();  // stage st free for reuse by issue at i+1
    }

    // ---- finalize + store ctx ----
    const float inv0 = 1.0f / l0;
    const float inv1 = 1.0f / l1;
    const size_t r0 = row_base + q0 + wid * 16 + g;
    const size_t r1 = r0 + 8;
#pragma unroll
    for (int j = 0; j < 8; j++) {
        float2 v0 = {o[j][0] * inv0, o[j][1] * inv0};
        float2 v1 = {o[j][2] * inv1, o[j][3] * inv1};
        *(float2*)(ctx + r0 * HID + hoff + j * 8 + c2) = v0;
        *(float2*)(ctx + r1 * HID + hoff + j * 8 + c2) = v1;
    }
}

// ---------------------------------------------------------------------------
extern "C" void kernel_launch(void* const* d_in, const int* in_sizes, int n_in,
                              void* d_out, int out_size)
{
    const float* hidden = (const float*)d_in[0];
    const float* mask   = (const float*)d_in[1];
    const float* w_attn = (const float*)d_in[2];
    const float* b_attn = (const float*)d_in[3];
    const float* w_proj = (const float*)d_in[4];
    const float* b_proj = (const float*)d_in[5];
    float* out = (float*)d_out;

    float* ctx = nullptr;
    __nv_bfloat16 *qkvh = nullptr, *qkvl = nullptr, *vTh = nullptr, *vTl = nullptr;
    __nv_bfloat16 *wTh = nullptr, *wTl = nullptr, *pTh = nullptr, *pTl = nullptr;
    cudaGetSymbolAddress((void**)&ctx,  g_ctx);
    cudaGetSymbolAddress((void**)&qkvh, g_qkvh);
    cudaGetSymbolAddress((void**)&qkvl, g_qkvl);
    cudaGetSymbolAddress((void**)&vTh,  g_vTh);
    cudaGetSymbolAddress((void**)&vTl,  g_vTl);
    cudaGetSymbolAddress((void**)&wTh,  g_wTh);
    cudaGetSymbolAddress((void**)&wTl,  g_wTl);
    cudaGetSymbolAddress((void**)&pTh,  g_pTh);
    cudaGetSymbolAddress((void**)&pTl,  g_pTl);

    static bool attr_set = false;
    if (!attr_set) {
        cudaFuncSetAttribute(flash_attn_tc,
                             cudaFuncAttributeMaxDynamicSharedMemorySize, SMEM_TOT);
        attr_set = true;
    }

    // 0) Weight prep (transpose + bf16 split)
    transpose_split<<<dim3(QKV_N / 32, HID / 32), dim3(32, 8)>>>(w_attn, wTh, wTl, HID, QKV_N);
    transpose_split<<<dim3(HID / 32, HID / 32), dim3(32, 8)>>>(w_proj, pTh, pTl, HID, HID);

    // 1) QKV GEMM -> split-bf16 qkv
    gemm_bf16s<<<dim3(QKV_N / 128, M_TOT / 128), 256>>>(
        hidden, wTh, wTl, b_attn, nullptr, qkvh, qkvl, HID, QKV_N);

    // 1b) V transpose -> [b][h*64+d][key]
    transpose_v<<<dim3(SEQ / 32, HID / 32, BATCH), dim3(32, 8)>>>(qkvh, qkvl, vTh, vTl);

    // 2) Flash attention (cp.async pipelined) -> ctx
    flash_attn_tc<<<dim3(SEQ / 128, NHEAD, BATCH), 256, SMEM_TOT>>>(
        qkvh, qkvl, vTh, vTl, mask, ctx);

    // 3) out = ctx @ c_proj_w + b
    gemm_bf16s<<<dim3(HID / 128, M_TOT / 128), 256>>>(
        ctx, pTh, pTl, b_proj, out, nullptr, nullptr, HID, HID);
}

// round 7
// speedup vs baseline: 3.0162x; 1.0645x over previous
#include <cuda_runtime.h>
#include <cuda_bf16.h>
#include <cstdint>

// Problem constants
#define BATCH   2
#define SEQ     2048
#define HID     1024
#define NHEAD   16
#define HDIM    64
#define QKV_N   (3 * HID)     // 3072
#define M_TOT   (BATCH * SEQ) // 4096

// Scratch (device globals: allocation-free rule)
__device__ __nv_bfloat16 g_hh[(size_t)M_TOT * HID];           // hidden split hi
__device__ __nv_bfloat16 g_hl[(size_t)M_TOT * HID];           // hidden split lo
__device__ __nv_bfloat16 g_qkvh[(size_t)M_TOT * QKV_N];       // qkv split hi
__device__ __nv_bfloat16 g_qkvl[(size_t)M_TOT * QKV_N];       // qkv split lo
__device__ __nv_bfloat16 g_ctxh[(size_t)M_TOT * HID];         // ctx split hi
__device__ __nv_bfloat16 g_ctxl[(size_t)M_TOT * HID];         // ctx split lo
__device__ __nv_bfloat16 g_vTh[(size_t)BATCH * HID * SEQ];    // V^T hi [b][h*64+d][key]
__device__ __nv_bfloat16 g_vTl[(size_t)BATCH * HID * SEQ];    // V^T lo
__device__ __nv_bfloat16 g_wTh[(size_t)QKV_N * HID];
__device__ __nv_bfloat16 g_wTl[(size_t)QKV_N * HID];
__device__ __nv_bfloat16 g_pTh[(size_t)HID * HID];
__device__ __nv_bfloat16 g_pTl[(size_t)HID * HID];

// ---------------------------------------------------------------------------
// Helpers
// ---------------------------------------------------------------------------
__device__ __forceinline__ void split_bf16(float a, __nv_bfloat16& h, __nv_bfloat16& l) {
    h = __float2bfloat16_rn(a);
    l = __float2bfloat16_rn(a - __bfloat162float(h));
}

__device__ __forceinline__ void pack_split(float x, float y, uint32_t& hi, uint32_t& lo) {
    __nv_bfloat16 hx, lx, hy, ly;
    split_bf16(x, hx, lx);
    split_bf16(y, hy, ly);
    __nv_bfloat162 ph = {hx, hy}, pl = {lx, ly};
    hi = *(uint32_t*)&ph;
    lo = *(uint32_t*)&pl;
}

__device__ __forceinline__ void mma_bf16(
    float& d0, float& d1, float& d2, float& d3,
    uint32_t a0, uint32_t a1, uint32_t a2, uint32_t a3,
    uint32_t b0, uint32_t b1)
{
    asm volatile(
        "mma.sync.aligned.m16n8k16.row.col.f32.bf16.bf16.f32 "
        "{%0,%1,%2,%3}, {%4,%5,%6,%7}, {%8,%9}, {%0,%1,%2,%3};"
        : "+f"(d0), "+f"(d1), "+f"(d2), "+f"(d3)
        : "r"(a0), "r"(a1), "r"(a2), "r"(a3), "r"(b0), "r"(b1));
}

__device__ __forceinline__ uint32_t smem_u32(const void* p) {
    uint32_t a;
    asm("{ .reg .u64 t; cvta.to.shared.u64 t, %1; cvt.u32.u64 %0, t; }"
        : "=r"(a) : "l"(p));
    return a;
}

__device__ __forceinline__ void cp_async16(uint32_t dst, const void* src) {
    asm volatile("cp.async.ca.shared.global [%0], [%1], 16;" :: "r"(dst), "l"(src));
}
#define CP_COMMIT() asm volatile("cp.async.commit_group;" ::: "memory")
#define CP_WAIT(n)  asm volatile("cp.async.wait_group %0;" :: "n"(n) : "memory")

// ---------------------------------------------------------------------------
// Prep kernels
// ---------------------------------------------------------------------------
__global__ void split_act(const float* __restrict__ X,
                          __nv_bfloat16* __restrict__ Xh,
                          __nv_bfloat16* __restrict__ Xl)
{
    const size_t i = ((size_t)blockIdx.x * 256 + threadIdx.x) * 4;
    float4 v = *(const float4*)(X + i);
    uint32_t h0, l0, h1, l1;
    pack_split(v.x, v.y, h0, l0);
    pack_split(v.z, v.w, h1, l1);
    uint2 ph = {h0, h1}, pl = {l0, l1};
    *(uint2*)(Xh + i) = ph;
    *(uint2*)(Xl + i) = pl;
}

__global__ void transpose_split(const float* __restrict__ B,
                                __nv_bfloat16* __restrict__ Bh,
                                __nv_bfloat16* __restrict__ Bl,
                                int K, int N)
{
    __shared__ float t[32][33];
    const int n0 = blockIdx.x * 32, k0 = blockIdx.y * 32;
    const int x = threadIdx.x, y = threadIdx.y; // (32,8)
#pragma unroll
    for (int i = y; i < 32; i += 8)
        t[i][x] = B[(size_t)(k0 + i) * N + n0 + x];
    __syncthreads();
#pragma unroll
    for (int i = y; i < 32; i += 8) {
        float a = t[x][i];
        __nv_bfloat16 h, l;
        split_bf16(a, h, l);
        Bh[(size_t)(n0 + i) * K + k0 + x] = h;
        Bl[(size_t)(n0 + i) * K + k0 + x] = l;
    }
}

__global__ void transpose_v(const __nv_bfloat16* __restrict__ qh,
                            const __nv_bfloat16* __restrict__ ql,
                            __nv_bfloat16* __restrict__ vTh,
                            __nv_bfloat16* __restrict__ vTl)
{
    __shared__ __nv_bfloat16 th[32][34];
    __shared__ __nv_bfloat16 tl[32][34];
    const int b  = blockIdx.z;
    const int k0 = blockIdx.x * 32;   // key
    const int d0 = blockIdx.y * 32;   // dim (h*64+d)
    const int x = threadIdx.x, y = threadIdx.y; // (32,8)
#pragma unroll
    for (int i = y; i < 32; i += 8) {
        const size_t src = (size_t)(b * SEQ + k0 + i) * QKV_N + 2 * HID + d0 + x;
        th[i][x] = qh[src];
        tl[i][x] = ql[src];
    }
    __syncthreads();
#pragma unroll
    for (int i = y; i < 32; i += 8) {
        const size_t dst = ((size_t)b * HID + d0 + i) * SEQ + k0 + x;
        vTh[dst] = th[x][i];
        vTl[dst] = tl[x][i];
    }
}

// ---------------------------------------------------------------------------
// All-bf16 cp.async double-buffered GEMM.
// A: Ah/Al [M][K] bf16.  B: Bth/Btl [N][K] bf16.  Tile 128x128, KC=32.
// Output fp32 C (Ch==nullptr) or split bf16 (Ch/Cl).
// Dynamic SMEM: 2 stages x (AH,AL,BH,BL each 128x40 bf16 = 10240B) = 81920B.
// ---------------------------------------------------------------------------
#define G_AH 0
#define G_AL 10240
#define G_BH 20480
#define G_BL 30720
#define G_STAGE 40960
#define G_SMEM (2 * G_STAGE)

__global__ __launch_bounds__(256, 2) void gemm_bf16_pipe(
    const __nv_bfloat16* __restrict__ Ah, const __nv_bfloat16* __restrict__ Al,
    const __nv_bfloat16* __restrict__ Bth, const __nv_bfloat16* __restrict__ Btl,
    const float* __restrict__ bias, float* __restrict__ C,
    __nv_bfloat16* __restrict__ Ch, __nv_bfloat16* __restrict__ Cl,
    int K, int N)
{
    extern __shared__ char smem[];
    const uint32_t smem_base = smem_u32(smem);

    const int tid = threadIdx.x;
    const int wid = tid >> 5;
    const int lane = tid & 31;
    const int g  = lane >> 2;
    const int c2 = (lane & 3) * 2;
    const int warp_m = wid & 1;
    const int warp_n = wid >> 1;
    const int m0 = blockIdx.y * 128;
    const int n0 = blockIdx.x * 128;
    const int wm = warp_m * 64;
    const int wn = warp_n * 32;

    float acc[4][4][4];
#pragma unroll
    for (int mi = 0; mi < 4; mi++)
#pragma unroll
        for (int ni = 0; ni < 4; ni++)
#pragma unroll
            for (int r = 0; r < 4; r++) acc[mi][ni][r] = 0.0f;

    auto issue = [&](int k0, int st) {
        const uint32_t sb = smem_base + st * G_STAGE;
#pragma unroll
        for (int it = 0; it < 2; it++) {
            const int idx = tid + it * 256;   // 0..511
            const int r = idx >> 2;           // 0..127
            const int q = idx & 3;            // 16B chunk
            const size_t aoff = (size_t)(m0 + r) * K + k0 + q * 8;
            const size_t boff = (size_t)(n0 + r) * K + k0 + q * 8;
            const uint32_t d = r * 80 + q * 16;
            cp_async16(sb + G_AH + d, Ah + aoff);
            cp_async16(sb + G_AL + d, Al + aoff);
            cp_async16(sb + G_BH + d, Bth + boff);
            cp_async16(sb + G_BL + d, Btl + boff);
        }
        CP_COMMIT();
    };

    const int nchunks = K >> 5;
    issue(0, 0);

    for (int ic = 0; ic < nchunks; ic++) {
        const int st = ic & 1;
        if (ic + 1 < nchunks) {
            issue((ic + 1) << 5, st ^ 1);
            CP_WAIT(1);
        } else {
            CP_WAIT(0);
        }
        __syncthreads();

        const __nv_bfloat16* sAh = (const __nv_bfloat16*)(smem + st * G_STAGE + G_AH);
        const __nv_bfloat16* sAl = (const __nv_bfloat16*)(smem + st * G_STAGE + G_AL);
        const __nv_bfloat16* sBh = (const __nv_bfloat16*)(smem + st * G_STAGE + G_BH);
        const __nv_bfloat16* sBl = (const __nv_bfloat16*)(smem + st * G_STAGE + G_BL);

#pragma unroll
        for (int kk = 0; kk < 32; kk += 16) {
            uint32_t ah[4][4], al[4][4];
#pragma unroll
            for (int mi = 0; mi < 4; mi++) {
                const int R0 = wm + mi * 16 + g;
                const int R1 = R0 + 8;
                ah[mi][0] = *(const uint32_t*)(sAh + R0 * 40 + kk + c2);
                ah[mi][1] = *(const uint32_t*)(sAh + R1 * 40 + kk + c2);
                ah[mi][2] = *(const uint32_t*)(sAh + R0 * 40 + kk + 8 + c2);
                ah[mi][3] = *(const uint32_t*)(sAh + R1 * 40 + kk + 8 + c2);
                al[mi][0] = *(const uint32_t*)(sAl + R0 * 40 + kk + c2);
                al[mi][1] = *(const uint32_t*)(sAl + R1 * 40 + kk + c2);
                al[mi][2] = *(const uint32_t*)(sAl + R0 * 40 + kk + 8 + c2);
                al[mi][3] = *(const uint32_t*)(sAl + R1 * 40 + kk + 8 + c2);
            }
#pragma unroll
            for (int ni = 0; ni < 4; ni++) {
                const int nr = wn + ni * 8 + g;
                const uint32_t bh0 = *(const uint32_t*)(sBh + nr * 40 + kk + c2);
                const uint32_t bh1 = *(const uint32_t*)(sBh + nr * 40 + kk + 8 + c2);
                const uint32_t bl0 = *(const uint32_t*)(sBl + nr * 40 + kk + c2);
                const uint32_t bl1 = *(const uint32_t*)(sBl + nr * 40 + kk + 8 + c2);
#pragma unroll
                for (int mi = 0; mi < 4; mi++) {
                    mma_bf16(acc[mi][ni][0], acc[mi][ni][1], acc[mi][ni][2], acc[mi][ni][3],
                             ah[mi][0], ah[mi][1], ah[mi][2], ah[mi][3], bh0, bh1);
                    mma_bf16(acc[mi][ni][0], acc[mi][ni][1], acc[mi][ni][2], acc[mi][ni][3],
                             ah[mi][0], ah[mi][1], ah[mi][2], ah[mi][3], bl0, bl1);
                    mma_bf16(acc[mi][ni][0], acc[mi][ni][1], acc[mi][ni][2], acc[mi][ni][3],
                             al[mi][0], al[mi][1], al[mi][2], al[mi][3], bh0, bh1);
                }
            }
        }
        __syncthreads();
    }

    if (Ch) {
#pragma unroll
        for (int mi = 0; mi < 4; mi++) {
            const int row0 = m0 + wm + mi * 16 + g;
#pragma unroll
            for (int ni = 0; ni < 4; ni++) {
                const int colL = wn + ni * 8 + c2;
                const float b0 = __ldg(bias + n0 + colL);
                const float b1 = __ldg(bias + n0 + colL + 1);
                uint32_t h0, l0, h1, l1;
                pack_split(acc[mi][ni][0] + b0, acc[mi][ni][1] + b1, h0, l0);
                pack_split(acc[mi][ni][2] + b0, acc[mi][ni][3] + b1, h1, l1);
                const size_t o0 = (size_t)row0 * N + n0 + colL;
                const size_t o1 = (size_t)(row0 + 8) * N + n0 + colL;
                *(uint32_t*)(Ch + o0) = h0;
                *(uint32_t*)(Cl + o0) = l0;
                *(uint32_t*)(Ch + o1) = h1;
                *(uint32_t*)(Cl + o1) = l1;
            }
        }
    } else {
#pragma unroll
        for (int mi = 0; mi < 4; mi++) {
            const int row0 = m0 + wm + mi * 16 + g;
#pragma unroll
            for (int ni = 0; ni < 4; ni++) {
                const int colL = wn + ni * 8 + c2;
                const float b0 = __ldg(bias + n0 + colL);
                const float b1 = __ldg(bias + n0 + colL + 1);
                float2 v0 = {acc[mi][ni][0] + b0, acc[mi][ni][1] + b1};
                float2 v1 = {acc[mi][ni][2] + b0, acc[mi][ni][3] + b1};
                *(float2*)(C + (size_t)row0 * N + n0 + colL) = v0;
                *(float2*)(C + (size_t)(row0 + 8) * N + n0 + colL) = v1;
            }
        }
    }
}

// ===========================================================================
// Flash attention (round-6 proven) — epilogue now emits split-bf16 ctx.
// ===========================================================================
#define KH_OFF   0
#define KL_OFF   9216
#define VH_OFF   18432
#define VL_OFF   27648
#define STAGE_SZ 36864
#define MASK_OFF 73728
#define SMEM_TOT 74240

__global__ __launch_bounds__(256, 2) void flash_attn_tc(
    const __nv_bfloat16* __restrict__ qkvh, const __nv_bfloat16* __restrict__ qkvl,
    const __nv_bfloat16* __restrict__ vTh,  const __nv_bfloat16* __restrict__ vTl,
    const float* __restrict__ mask,
    __nv_bfloat16* __restrict__ ctxh, __nv_bfloat16* __restrict__ ctxl)
{
    extern __shared__ char smem[];
    const uint32_t smem_base = smem_u32(smem);

    const int tid  = threadIdx.x;
    const int wid  = tid >> 5;
    const int lane = tid & 31;
    const int g    = lane >> 2;
    const int c2   = (lane & 3) * 2;
    const int q0   = blockIdx.x * 128;
    const int h    = blockIdx.y;
    const int b    = blockIdx.z;

    const size_t row_base = (size_t)b * SEQ;
    const int hoff  = h * HDIM;
    const int khoff = HID + hoff;
    const size_t vrow_base = ((size_t)b * HID + hoff) * SEQ;

    uint32_t qh[4][4], ql[4][4];
    {
        const __nv_bfloat16* qr0 = qkvh + (row_base + q0 + wid * 16 + g) * QKV_N + hoff;
        const __nv_bfloat16* qr1 = qr0 + 8 * QKV_N;
        const __nv_bfloat16* lr0 = qkvl + (row_base + q0 + wid * 16 + g) * QKV_N + hoff;
        const __nv_bfloat16* lr1 = lr0 + 8 * QKV_N;
#pragma unroll
        for (int s = 0; s < 4; s++) {
            qh[s][0] = *(const uint32_t*)(qr0 + s * 16 + c2);
            qh[s][1] = *(const uint32_t*)(qr1 + s * 16 + c2);
            qh[s][2] = *(const uint32_t*)(qr0 + s * 16 + 8 + c2);
            qh[s][3] = *(const uint32_t*)(qr1 + s * 16 + 8 + c2);
            ql[s][0] = *(const uint32_t*)(lr0 + s * 16 + c2);
            ql[s][1] = *(const uint32_t*)(lr1 + s * 16 + c2);
            ql[s][2] = *(const uint32_t*)(lr0 + s * 16 + 8 + c2);
            ql[s][3] = *(const uint32_t*)(lr1 + s * 16 + 8 + c2);
        }
    }

    float o[8][4];
#pragma unroll
    for (int j = 0; j < 8; j++)
#pragma unroll
        for (int r = 0; r < 4; r++) o[j][r] = 0.0f;
    float m0 = -1e30f, m1 = -1e30f, l0 = 0.0f, l1 = 0.0f;

    auto issue_tile = [&](int k0, int st) {
        const uint32_t sb = smem_base + st * STAGE_SZ;
#pragma unroll
        for (int it = 0; it < 4; it++) {
            const int idx = tid + it * 256;
            const int bufsel = idx >> 9;
            const int j = idx & 511;
            const int r = j >> 3;
            const int q = j & 7;
            const __nv_bfloat16* src =
                (bufsel ? qkvl : qkvh) + (row_base + k0 + r) * QKV_N + khoff + q * 8;
            cp_async16(sb + (bufsel ? KL_OFF : KH_OFF) + r * 144 + q * 16, src);
        }
#pragma unroll
        for (int it = 0; it < 4; it++) {
            const int idx = tid + it * 256;
            const int bufsel = idx >> 9;
            const int j = idx & 511;
            const int r = j >> 3;
            const int q = j & 7;
            const __nv_bfloat16* src =
                (bufsel ? vTl : vTh) + vrow_base + (size_t)r * SEQ + k0 + q * 8;
            cp_async16(sb + (bufsel ? VL_OFF : VH_OFF) + r * 144 + q * 16, src);
        }
        if (tid < 64)
            *(float*)(smem + MASK_OFF + st * 256 + tid * 4) = mask[(size_t)b * SEQ + k0 + tid];
        CP_COMMIT();
    };

    issue_tile(0, 0);

    for (int i = 0; i < SEQ / 64; i++) {
        const int st = i & 1;
        if (i < SEQ / 64 - 1) {
            issue_tile((i + 1) * 64, st ^ 1);
            CP_WAIT(1);
        } else {
            CP_WAIT(0);
        }
        __syncthreads();

        const __nv_bfloat16* Kh = (const __nv_bfloat16*)(smem + st * STAGE_SZ + KH_OFF);
        const __nv_bfloat16* Kl = (const __nv_bfloat16*)(smem + st * STAGE_SZ + KL_OFF);
        const __nv_bfloat16* Vh = (const __nv_bfloat16*)(smem + st * STAGE_SZ + VH_OFF);
        const __nv_bfloat16* Vl = (const __nv_bfloat16*)(smem + st * STAGE_SZ + VL_OFF);
        const float* sMask = (const float*)(smem + MASK_OFF + st * 256);

        float sc[8][4];
#pragma unroll
        for (int j = 0; j < 8; j++)
#pragma unroll
            for (int r = 0; r < 4; r++) sc[j][r] = 0.0f;

#pragma unroll
        for (int j = 0; j < 8; j++) {
            const int nr = j * 8 + g;
#pragma unroll
            for (int s = 0; s < 4; s++) {
                const uint32_t bh0 = *(const uint32_t*)(Kh + nr * 72 + s * 16 + c2);
                const uint32_t bh1 = *(const uint32_t*)(Kh + nr * 72 + s * 16 + 8 + c2);
                const uint32_t bl0 = *(const uint32_t*)(Kl + nr * 72 + s * 16 + c2);
                const uint32_t bl1 = *(const uint32_t*)(Kl + nr * 72 + s * 16 + 8 + c2);
                mma_bf16(sc[j][0], sc[j][1], sc[j][2], sc[j][3],
                         qh[s][0], qh[s][1], qh[s][2], qh[s][3], bh0, bh1);
                mma_bf16(sc[j][0], sc[j][1], sc[j][2], sc[j][3],
                         qh[s][0], qh[s][1], qh[s][2], qh[s][3], bl0, bl1);
                mma_bf16(sc[j][0], sc[j][1], sc[j][2], sc[j][3],
                         ql[s][0], ql[s][1], ql[s][2], ql[s][3], bh0, bh1);
            }
        }

        float rmax0 = -1e30f, rmax1 = -1e30f;
#pragma unroll
        for (int j = 0; j < 8; j++) {
            const float mv0 = sMask[j * 8 + c2];
            const float mv1 = sMask[j * 8 + c2 + 1];
            sc[j][0] = sc[j][0] * 0.125f + mv0;
            sc[j][1] = sc[j][1] * 0.125f + mv1;
            sc[j][2] = sc[j][2] * 0.125f + mv0;
            sc[j][3] = sc[j][3] * 0.125f + mv1;
            rmax0 = fmaxf(rmax0, fmaxf(sc[j][0], sc[j][1]));
            rmax1 = fmaxf(rmax1, fmaxf(sc[j][2], sc[j][3]));
        }
#pragma unroll
        for (int off = 1; off <= 2; off <<= 1) {
            rmax0 = fmaxf(rmax0, __shfl_xor_sync(0xffffffffu, rmax0, off));
            rmax1 = fmaxf(rmax1, __shfl_xor_sync(0xffffffffu, rmax1, off));
        }
        const float nm0 = fmaxf(m0, rmax0);
        const float nm1 = fmaxf(m1, rmax1);
        const float a0 = __expf(m0 - nm0);
        const float a1 = __expf(m1 - nm1);

        float rs0 = 0.0f, rs1 = 0.0f;
#pragma unroll
        for (int j = 0; j < 8; j++) {
            sc[j][0] = __expf(sc[j][0] - nm0);
            sc[j][1] = __expf(sc[j][1] - nm0);
            sc[j][2] = __expf(sc[j][2] - nm1);
            sc[j][3] = __expf(sc[j][3] - nm1);
            rs0 += sc[j][0] + sc[j][1];
            rs1 += sc[j][2] + sc[j][3];
        }
#pragma unroll
        for (int off = 1; off <= 2; off <<= 1) {
            rs0 += __shfl_xor_sync(0xffffffffu, rs0, off);
            rs1 += __shfl_xor_sync(0xffffffffu, rs1, off);
        }
        l0 = l0 * a0 + rs0;
        l1 = l1 * a1 + rs1;
        m0 = nm0;
        m1 = nm1;
#pragma unroll
        for (int j = 0; j < 8; j++) {
            o[j][0] *= a0; o[j][1] *= a0;
            o[j][2] *= a1; o[j][3] *= a1;
        }

        uint32_t ph[4][4], pl[4][4];
#pragma unroll
        for (int s = 0; s < 4; s++) {
            pack_split(sc[2 * s][0],     sc[2 * s][1],     ph[s][0], pl[s][0]);
            pack_split(sc[2 * s][2],     sc[2 * s][3],     ph[s][1], pl[s][1]);
            pack_split(sc[2 * s + 1][0], sc[2 * s + 1][1], ph[s][2], pl[s][2]);
            pack_split(sc[2 * s + 1][2], sc[2 * s + 1][3], ph[s][3], pl[s][3]);
        }

#pragma unroll
        for (int j = 0; j < 8; j++) {
            const int nr = j * 8 + g;
#pragma unroll
            for (int s = 0; s < 4; s++) {
                const uint32_t bh0 = *(const uint32_t*)(Vh + nr * 72 + s * 16 + c2);
                const uint32_t bh1 = *(const uint32_t*)(Vh + nr * 72 + s * 16 + 8 + c2);
                const uint32_t bl0 = *(const uint32_t*)(Vl + nr * 72 + s * 16 + c2);
                const uint32_t bl1 = *(const uint32_t*)(Vl + nr * 72 + s * 16 + 8 + c2);
                mma_bf16(o[j][0], o[j][1], o[j][2], o[j][3],
                         ph[s][0], ph[s][1], ph[s][2], ph[s][3], bh0, bh1);
                mma_bf16(o[j][0], o[j][1], o[j][2], o[j][3],
                         ph[s][0], ph[s][1], ph[s][2], ph[s][3], bl0, bl1);
                mma_bf16(o[j][0], o[j][1], o[j][2], o[j][3],
                         pl[s][0], pl[s][1], pl[s][2], pl[s][3], bh0, bh1);
            }
        }
        __syncthreads();
    }

    // ---- finalize + store split-bf16 ctx ----
    const float inv0 = 1.0f / l0;
    const float inv1 = 1.0f / l1;
    const size_t r0 = row_base + q0 + wid * 16 + g;
    const size_t r1 = r0 + 8;
#pragma unroll
    for (int j = 0; j < 8; j++) {
        uint32_t h0, lo0, h1, lo1;
        pack_split(o[j][0] * inv0, o[j][1] * inv0, h0, lo0);
        pack_split(o[j][2] * inv1, o[j][3] * inv1, h1, lo1);
        const size_t o0 = r0 * HID + hoff + j * 8 + c2;
        const size_t o1 = r1 * HID + hoff + j * 8 + c2;
        *(uint32_t*)(ctxh + o0) = h0;
        *(uint32_t*)(ctxl + o0) = lo0;
        *(uint32_t*)(ctxh + o1) = h1;
        *(uint32_t*)(ctxl + o1) = lo1;
    }
}

// ---------------------------------------------------------------------------
extern "C" void kernel_launch(void* const* d_in, const int* in_sizes, int n_in,
                              void* d_out, int out_size)
{
    const float* hidden = (const float*)d_in[0];
    const float* mask   = (const float*)d_in[1];
    const float* w_attn = (const float*)d_in[2];
    const float* b_attn = (const float*)d_in[3];
    const float* w_proj = (const float*)d_in[4];
    const float* b_proj = (const float*)d_in[5];
    float* out = (float*)d_out;

    __nv_bfloat16 *hh, *hl, *qkvh, *qkvl, *ctxh, *ctxl, *vTh, *vTl, *wTh, *wTl, *pTh, *pTl;
    cudaGetSymbolAddress((void**)&hh,   g_hh);
    cudaGetSymbolAddress((void**)&hl,   g_hl);
    cudaGetSymbolAddress((void**)&qkvh, g_qkvh);
    cudaGetSymbolAddress((void**)&qkvl, g_qkvl);
    cudaGetSymbolAddress((void**)&ctxh, g_ctxh);
    cudaGetSymbolAddress((void**)&ctxl, g_ctxl);
    cudaGetSymbolAddress((void**)&vTh,  g_vTh);
    cudaGetSymbolAddress((void**)&vTl,  g_vTl);
    cudaGetSymbolAddress((void**)&wTh,  g_wTh);
    cudaGetSymbolAddress((void**)&wTl,  g_wTl);
    cudaGetSymbolAddress((void**)&pTh,  g_pTh);
    cudaGetSymbolAddress((void**)&pTl,  g_pTl);

    static bool attr_set = false;
    if (!attr_set) {
        cudaFuncSetAttribute(flash_attn_tc,
                             cudaFuncAttributeMaxDynamicSharedMemorySize, SMEM_TOT);
        cudaFuncSetAttribute(gemm_bf16_pipe,
                             cudaFuncAttributeMaxDynamicSharedMemorySize, G_SMEM);
        attr_set = true;
    }

    // 0) Prep: weight transpose+split, activation split
    transpose_split<<<dim3(QKV_N / 32, HID / 32), dim3(32, 8)>>>(w_attn, wTh, wTl, HID, QKV_N);
    transpose_split<<<dim3(HID / 32, HID / 32), dim3(32, 8)>>>(w_proj, pTh, pTl, HID, HID);
    split_act<<<(M_TOT * HID) / 1024, 256>>>(hidden, hh, hl);

    // 1) QKV GEMM -> split-bf16 qkv
    gemm_bf16_pipe<<<dim3(QKV_N / 128, M_TOT / 128), 256, G_SMEM>>>(
        hh, hl, wTh, wTl, b_attn, nullptr, qkvh, qkvl, HID, QKV_N);

    // 1b) V transpose -> [b][h*64+d][key]
    transpose_v<<<dim3(SEQ / 32, HID / 32, BATCH), dim3(32, 8)>>>(qkvh, qkvl, vTh, vTl);

    // 2) Flash attention -> split-bf16 ctx
    flash_attn_tc<<<dim3(SEQ / 128, NHEAD, BATCH), 256, SMEM_TOT>>>(
        qkvh, qkvl, vTh, vTl, mask, ctxh, ctxl);

    // 3) out = ctx @ c_proj_w + b  (fp32 output)
    gemm_bf16_pipe<<<dim3(HID / 128, M_TOT / 128), 256, G_SMEM>>>(
        ctxh, ctxl, pTh, pTl, b_proj, out, nullptr, nullptr, HID, HID);
}

// round 8
// speedup vs baseline: 3.2583x; 1.0803x over previous
#include <cuda_runtime.h>
#include <cuda_bf16.h>
#include <cstdint>

// Problem constants
#define BATCH   2
#define SEQ     2048
#define HID     1024
#define NHEAD   16
#define HDIM    64
#define QKV_N   (3 * HID)     // 3072
#define M_TOT   (BATCH * SEQ) // 4096

// Scratch (device globals: allocation-free rule)
__device__ __nv_bfloat16 g_hh[(size_t)M_TOT * HID];
__device__ __nv_bfloat16 g_hl[(size_t)M_TOT * HID];
__device__ __nv_bfloat16 g_qkvh[(size_t)M_TOT * QKV_N];
__device__ __nv_bfloat16 g_qkvl[(size_t)M_TOT * QKV_N];
__device__ __nv_bfloat16 g_ctxh[(size_t)M_TOT * HID];
__device__ __nv_bfloat16 g_ctxl[(size_t)M_TOT * HID];
__device__ __nv_bfloat16 g_vTh[(size_t)BATCH * HID * SEQ];
__device__ __nv_bfloat16 g_vTl[(size_t)BATCH * HID * SEQ];
__device__ __nv_bfloat16 g_wTh[(size_t)QKV_N * HID];
__device__ __nv_bfloat16 g_wTl[(size_t)QKV_N * HID];
__device__ __nv_bfloat16 g_pTh[(size_t)HID * HID];
__device__ __nv_bfloat16 g_pTl[(size_t)HID * HID];

// ---------------------------------------------------------------------------
// Helpers
// ---------------------------------------------------------------------------
__device__ __forceinline__ void split_bf16(float a, __nv_bfloat16& h, __nv_bfloat16& l) {
    h = __float2bfloat16_rn(a);
    l = __float2bfloat16_rn(a - __bfloat162float(h));
}

__device__ __forceinline__ void pack_split(float x, float y, uint32_t& hi, uint32_t& lo) {
    __nv_bfloat16 hx, lx, hy, ly;
    split_bf16(x, hx, lx);
    split_bf16(y, hy, ly);
    __nv_bfloat162 ph = {hx, hy}, pl = {lx, ly};
    hi = *(uint32_t*)&ph;
    lo = *(uint32_t*)&pl;
}

__device__ __forceinline__ void mma_bf16(
    float& d0, float& d1, float& d2, float& d3,
    uint32_t a0, uint32_t a1, uint32_t a2, uint32_t a3,
    uint32_t b0, uint32_t b1)
{
    asm volatile(
        "mma.sync.aligned.m16n8k16.row.col.f32.bf16.bf16.f32 "
        "{%0,%1,%2,%3}, {%4,%5,%6,%7}, {%8,%9}, {%0,%1,%2,%3};"
        : "+f"(d0), "+f"(d1), "+f"(d2), "+f"(d3)
        : "r"(a0), "r"(a1), "r"(a2), "r"(a3), "r"(b0), "r"(b1));
}

__device__ __forceinline__ void ldsm_x4(uint32_t& r0, uint32_t& r1, uint32_t& r2, uint32_t& r3,
                                        uint32_t addr)
{
    asm volatile("ldmatrix.sync.aligned.m8n8.x4.shared.b16 {%0,%1,%2,%3}, [%4];"
                 : "=r"(r0), "=r"(r1), "=r"(r2), "=r"(r3) : "r"(addr));
}

__device__ __forceinline__ uint32_t smem_u32(const void* p) {
    uint32_t a;
    asm("{ .reg .u64 t; cvta.to.shared.u64 t, %1; cvt.u32.u64 %0, t; }"
        : "=r"(a) : "l"(p));
    return a;
}

__device__ __forceinline__ void cp_async16(uint32_t dst, const void* src) {
    asm volatile("cp.async.ca.shared.global [%0], [%1], 16;" :: "r"(dst), "l"(src));
}
#define CP_COMMIT() asm volatile("cp.async.commit_group;" ::: "memory")
#define CP_WAIT(n)  asm volatile("cp.async.wait_group %0;" :: "n"(n) : "memory")

// ---------------------------------------------------------------------------
// Prep kernels
// ---------------------------------------------------------------------------
__global__ void split_act(const float* __restrict__ X,
                          __nv_bfloat16* __restrict__ Xh,
                          __nv_bfloat16* __restrict__ Xl)
{
    const size_t i = ((size_t)blockIdx.x * 256 + threadIdx.x) * 4;
    float4 v = *(const float4*)(X + i);
    uint32_t h0, l0, h1, l1;
    pack_split(v.x, v.y, h0, l0);
    pack_split(v.z, v.w, h1, l1);
    uint2 ph = {h0, h1}, pl = {l0, l1};
    *(uint2*)(Xh + i) = ph;
    *(uint2*)(Xl + i) = pl;
}

__global__ void transpose_split(const float* __restrict__ B,
                                __nv_bfloat16* __restrict__ Bh,
                                __nv_bfloat16* __restrict__ Bl,
                                int K, int N)
{
    __shared__ float t[32][33];
    const int n0 = blockIdx.x * 32, k0 = blockIdx.y * 32;
    const int x = threadIdx.x, y = threadIdx.y; // (32,8)
#pragma unroll
    for (int i = y; i < 32; i += 8)
        t[i][x] = B[(size_t)(k0 + i) * N + n0 + x];
    __syncthreads();
#pragma unroll
    for (int i = y; i < 32; i += 8) {
        float a = t[x][i];
        __nv_bfloat16 h, l;
        split_bf16(a, h, l);
        Bh[(size_t)(n0 + i) * K + k0 + x] = h;
        Bl[(size_t)(n0 + i) * K + k0 + x] = l;
    }
}

__global__ void transpose_v(const __nv_bfloat16* __restrict__ qh,
                            const __nv_bfloat16* __restrict__ ql,
                            __nv_bfloat16* __restrict__ vTh,
                            __nv_bfloat16* __restrict__ vTl)
{
    __shared__ __nv_bfloat16 th[32][34];
    __shared__ __nv_bfloat16 tl[32][34];
    const int b  = blockIdx.z;
    const int k0 = blockIdx.x * 32;
    const int d0 = blockIdx.y * 32;
    const int x = threadIdx.x, y = threadIdx.y;
#pragma unroll
    for (int i = y; i < 32; i += 8) {
        const size_t src = (size_t)(b * SEQ + k0 + i) * QKV_N + 2 * HID + d0 + x;
        th[i][x] = qh[src];
        tl[i][x] = ql[src];
    }
    __syncthreads();
#pragma unroll
    for (int i = y; i < 32; i += 8) {
        const size_t dst = ((size_t)b * HID + d0 + i) * SEQ + k0 + x;
        vTh[dst] = th[x][i];
        vTl[dst] = tl[x][i];
    }
}

// ---------------------------------------------------------------------------
// All-bf16 cp.async GEMM with ldmatrix fragments, single-sync pipeline.
// ---------------------------------------------------------------------------
#define G_AH 0
#define G_AL 10240
#define G_BH 20480
#define G_BL 30720
#define G_STAGE 40960
#define G_SMEM (2 * G_STAGE)

__global__ __launch_bounds__(256, 2) void gemm_bf16_pipe(
    const __nv_bfloat16* __restrict__ Ah, const __nv_bfloat16* __restrict__ Al,
    const __nv_bfloat16* __restrict__ Bth, const __nv_bfloat16* __restrict__ Btl,
    const float* __restrict__ bias, float* __restrict__ C,
    __nv_bfloat16* __restrict__ Ch, __nv_bfloat16* __restrict__ Cl,
    int K, int N)
{
    extern __shared__ char smem[];
    const uint32_t smem_base = smem_u32(smem);

    const int tid = threadIdx.x;
    const int wid = tid >> 5;
    const int lane = tid & 31;
    const int g  = lane >> 2;
    const int c2 = (lane & 3) * 2;
    const int warp_m = wid & 1;
    const int warp_n = wid >> 1;
    const int m0 = blockIdx.y * 128;
    const int n0 = blockIdx.x * 128;
    const int wm = warp_m * 64;
    const int wn = warp_n * 32;

    // ldmatrix per-lane base offsets (bytes within stage buffer)
    const int lrA = lane & 15;
    const int lcA = (lane >> 4) * 8;
    uint32_t offA[4];
#pragma unroll
    for (int mi = 0; mi < 4; mi++)
        offA[mi] = (uint32_t)(((wm + mi * 16 + lrA) * 40 + lcA) * 2);
    uint32_t offB[2];
#pragma unroll
    for (int p = 0; p < 2; p++)
        offB[p] = (uint32_t)(((wn + p * 16 + ((lane >> 4) & 1) * 8 + (lane & 7)) * 40
                              + ((lane >> 3) & 1) * 8) * 2);

    float acc[4][4][4];
#pragma unroll
    for (int mi = 0; mi < 4; mi++)
#pragma unroll
        for (int ni = 0; ni < 4; ni++)
#pragma unroll
            for (int r = 0; r < 4; r++) acc[mi][ni][r] = 0.0f;

    auto issue = [&](int k0, int st) {
        const uint32_t sb = smem_base + st * G_STAGE;
#pragma unroll
        for (int it = 0; it < 2; it++) {
            const int idx = tid + it * 256;
            const int r = idx >> 2;
            const int q = idx & 3;
            const size_t aoff = (size_t)(m0 + r) * K + k0 + q * 8;
            const size_t boff = (size_t)(n0 + r) * K + k0 + q * 8;
            const uint32_t d = r * 80 + q * 16;
            cp_async16(sb + G_AH + d, Ah + aoff);
            cp_async16(sb + G_AL + d, Al + aoff);
            cp_async16(sb + G_BH + d, Bth + boff);
            cp_async16(sb + G_BL + d, Btl + boff);
        }
        CP_COMMIT();
    };

    const int nchunks = K >> 5;
    issue(0, 0);

    for (int ic = 0; ic < nchunks; ic++) {
        const int st = ic & 1;
        CP_WAIT(0);
        __syncthreads();
        if (ic + 1 < nchunks) issue((ic + 1) << 5, st ^ 1);

        const uint32_t sb = smem_base + st * G_STAGE;

#pragma unroll
        for (int kk = 0; kk < 32; kk += 16) {
            uint32_t ah[4][4], al[4][4];
#pragma unroll
            for (int mi = 0; mi < 4; mi++) {
                ldsm_x4(ah[mi][0], ah[mi][1], ah[mi][2], ah[mi][3],
                        sb + G_AH + offA[mi] + kk * 2);
                ldsm_x4(al[mi][0], al[mi][1], al[mi][2], al[mi][3],
                        sb + G_AL + offA[mi] + kk * 2);
            }
#pragma unroll
            for (int p = 0; p < 2; p++) {
                uint32_t bh[4], bl[4];
                ldsm_x4(bh[0], bh[1], bh[2], bh[3], sb + G_BH + offB[p] + kk * 2);
                ldsm_x4(bl[0], bl[1], bl[2], bl[3], sb + G_BL + offB[p] + kk * 2);
#pragma unroll
                for (int t = 0; t < 2; t++) {
                    const int ni = 2 * p + t;
                    const uint32_t bh0 = bh[2 * t], bh1 = bh[2 * t + 1];
                    const uint32_t bl0 = bl[2 * t], bl1 = bl[2 * t + 1];
#pragma unroll
                    for (int mi = 0; mi < 4; mi++) {
                        mma_bf16(acc[mi][ni][0], acc[mi][ni][1], acc[mi][ni][2], acc[mi][ni][3],
                                 ah[mi][0], ah[mi][1], ah[mi][2], ah[mi][3], bh0, bh1);
                        mma_bf16(acc[mi][ni][0], acc[mi][ni][1], acc[mi][ni][2], acc[mi][ni][3],
                                 ah[mi][0], ah[mi][1], ah[mi][2], ah[mi][3], bl0, bl1);
                        mma_bf16(acc[mi][ni][0], acc[mi][ni][1], acc[mi][ni][2], acc[mi][ni][3],
                                 al[mi][0], al[mi][1], al[mi][2], al[mi][3], bh0, bh1);
                    }
                }
            }
        }
    }

    if (Ch) {
#pragma unroll
        for (int mi = 0; mi < 4; mi++) {
            const int row0 = m0 + wm + mi * 16 + g;
#pragma unroll
            for (int ni = 0; ni < 4; ni++) {
                const int colL = wn + ni * 8 + c2;
                const float b0 = __ldg(bias + n0 + colL);
                const float b1 = __ldg(bias + n0 + colL + 1);
                uint32_t h0, l0, h1, l1;
                pack_split(acc[mi][ni][0] + b0, acc[mi][ni][1] + b1, h0, l0);
                pack_split(acc[mi][ni][2] + b0, acc[mi][ni][3] + b1, h1, l1);
                const size_t o0 = (size_t)row0 * N + n0 + colL;
                const size_t o1 = (size_t)(row0 + 8) * N + n0 + colL;
                *(uint32_t*)(Ch + o0) = h0;
                *(uint32_t*)(Cl + o0) = l0;
                *(uint32_t*)(Ch + o1) = h1;
                *(uint32_t*)(Cl + o1) = l1;
            }
        }
    } else {
#pragma unroll
        for (int mi = 0; mi < 4; mi++) {
            const int row0 = m0 + wm + mi * 16 + g;
#pragma unroll
            for (int ni = 0; ni < 4; ni++) {
                const int colL = wn + ni * 8 + c2;
                const float b0 = __ldg(bias + n0 + colL);
                const float b1 = __ldg(bias + n0 + colL + 1);
                float2 v0 = {acc[mi][ni][0] + b0, acc[mi][ni][1] + b1};
                float2 v1 = {acc[mi][ni][2] + b0, acc[mi][ni][3] + b1};
                *(float2*)(C + (size_t)row0 * N + n0 + colL) = v0;
                *(float2*)(C + (size_t)(row0 + 8) * N + n0 + colL) = v1;
            }
        }
    }
}

// ===========================================================================
// Flash attention: ldmatrix fragments + single-sync cp.async pipeline.
// ===========================================================================
#define KH_OFF   0
#define KL_OFF   9216
#define VH_OFF   18432
#define VL_OFF   27648
#define STAGE_SZ 36864
#define MASK_OFF 73728
#define SMEM_TOT 74240

__global__ __launch_bounds__(256, 2) void flash_attn_tc(
    const __nv_bfloat16* __restrict__ qkvh, const __nv_bfloat16* __restrict__ qkvl,
    const __nv_bfloat16* __restrict__ vTh,  const __nv_bfloat16* __restrict__ vTl,
    const float* __restrict__ mask,
    __nv_bfloat16* __restrict__ ctxh, __nv_bfloat16* __restrict__ ctxl)
{
    extern __shared__ char smem[];
    const uint32_t smem_base = smem_u32(smem);

    const int tid  = threadIdx.x;
    const int wid  = tid >> 5;
    const int lane = tid & 31;
    const int g    = lane >> 2;
    const int c2   = (lane & 3) * 2;
    const int q0   = blockIdx.x * 128;
    const int h    = blockIdx.y;
    const int b    = blockIdx.z;

    const size_t row_base = (size_t)b * SEQ;
    const int hoff  = h * HDIM;
    const int khoff = HID + hoff;
    const size_t vrow_base = ((size_t)b * HID + hoff) * SEQ;

    // ldmatrix per-lane offsets for K/V tiles (72-col stride), block p covers rows p*16..p*16+15
    uint32_t offKV[4];
#pragma unroll
    for (int p = 0; p < 4; p++)
        offKV[p] = (uint32_t)(((p * 16 + ((lane >> 4) & 1) * 8 + (lane & 7)) * 72
                               + ((lane >> 3) & 1) * 8) * 2);

    // Q fragments (direct bf16 loads)
    uint32_t qh[4][4], ql[4][4];
    {
        const __nv_bfloat16* qr0 = qkvh + (row_base + q0 + wid * 16 + g) * QKV_N + hoff;
        const __nv_bfloat16* qr1 = qr0 + 8 * QKV_N;
        const __nv_bfloat16* lr0 = qkvl + (row_base + q0 + wid * 16 + g) * QKV_N + hoff;
        const __nv_bfloat16* lr1 = lr0 + 8 * QKV_N;
#pragma unroll
        for (int s = 0; s < 4; s++) {
            qh[s][0] = *(const uint32_t*)(qr0 + s * 16 + c2);
            qh[s][1] = *(const uint32_t*)(qr1 + s * 16 + c2);
            qh[s][2] = *(const uint32_t*)(qr0 + s * 16 + 8 + c2);
            qh[s][3] = *(const uint32_t*)(qr1 + s * 16 + 8 + c2);
            ql[s][0] = *(const uint32_t*)(lr0 + s * 16 + c2);
            ql[s][1] = *(const uint32_t*)(lr1 + s * 16 + c2);
            ql[s][2] = *(const uint32_t*)(lr0 + s * 16 + 8 + c2);
            ql[s][3] = *(const uint32_t*)(lr1 + s * 16 + 8 + c2);
        }
    }

    float o[8][4];
#pragma unroll
    for (int j = 0; j < 8; j++)
#pragma unroll
        for (int r = 0; r < 4; r++) o[j][r] = 0.0f;
    float m0 = -1e30f, m1 = -1e30f, l0 = 0.0f, l1 = 0.0f;

    auto issue_tile = [&](int k0, int st) {
        const uint32_t sb = smem_base + st * STAGE_SZ;
#pragma unroll
        for (int it = 0; it < 4; it++) {
            const int idx = tid + it * 256;
            const int bufsel = idx >> 9;
            const int j = idx & 511;
            const int r = j >> 3;
            const int q = j & 7;
            const __nv_bfloat16* src =
                (bufsel ? qkvl : qkvh) + (row_base + k0 + r) * QKV_N + khoff + q * 8;
            cp_async16(sb + (bufsel ? KL_OFF : KH_OFF) + r * 144 + q * 16, src);
        }
#pragma unroll
        for (int it = 0; it < 4; it++) {
            const int idx = tid + it * 256;
            const int bufsel = idx >> 9;
            const int j = idx & 511;
            const int r = j >> 3;
            const int q = j & 7;
            const __nv_bfloat16* src =
                (bufsel ? vTl : vTh) + vrow_base + (size_t)r * SEQ + k0 + q * 8;
            cp_async16(sb + (bufsel ? VL_OFF : VH_OFF) + r * 144 + q * 16, src);
        }
        if (tid < 64)
            *(float*)(smem + MASK_OFF + st * 256 + tid * 4) = mask[(size_t)b * SEQ + k0 + tid];
        CP_COMMIT();
    };

    issue_tile(0, 0);

    for (int i = 0; i < SEQ / 64; i++) {
        const int st = i & 1;
        CP_WAIT(0);
        __syncthreads();
        if (i + 1 < SEQ / 64) issue_tile((i + 1) * 64, st ^ 1);

        const uint32_t sbKh = smem_base + st * STAGE_SZ + KH_OFF;
        const uint32_t sbKl = smem_base + st * STAGE_SZ + KL_OFF;
        const uint32_t sbVh = smem_base + st * STAGE_SZ + VH_OFF;
        const uint32_t sbVl = smem_base + st * STAGE_SZ + VL_OFF;
        const float* sMask = (const float*)(smem + MASK_OFF + st * 256);

        // ---- S = Q K^T (split, 3 passes), ldmatrix K frags ----
        float sc[8][4];
#pragma unroll
        for (int j = 0; j < 8; j++)
#pragma unroll
            for (int r = 0; r < 4; r++) sc[j][r] = 0.0f;

#pragma unroll
        for (int s = 0; s < 4; s++) {
#pragma unroll
            for (int p = 0; p < 4; p++) {
                uint32_t bh[4], bl[4];
                ldsm_x4(bh[0], bh[1], bh[2], bh[3], sbKh + offKV[p] + s * 32);
                ldsm_x4(bl[0], bl[1], bl[2], bl[3], sbKl + offKV[p] + s * 32);
#pragma unroll
                for (int t = 0; t < 2; t++) {
                    const int j = 2 * p + t;
                    mma_bf16(sc[j][0], sc[j][1], sc[j][2], sc[j][3],
                             qh[s][0], qh[s][1], qh[s][2], qh[s][3], bh[2 * t], bh[2 * t + 1]);
                    mma_bf16(sc[j][0], sc[j][1], sc[j][2], sc[j][3],
                             qh[s][0], qh[s][1], qh[s][2], qh[s][3], bl[2 * t], bl[2 * t + 1]);
                    mma_bf16(sc[j][0], sc[j][1], sc[j][2], sc[j][3],
                             ql[s][0], ql[s][1], ql[s][2], ql[s][3], bh[2 * t], bh[2 * t + 1]);
                }
            }
        }

        // ---- scale + mask + online softmax ----
        float rmax0 = -1e30f, rmax1 = -1e30f;
#pragma unroll
        for (int j = 0; j < 8; j++) {
            const float mv0 = sMask[j * 8 + c2];
            const float mv1 = sMask[j * 8 + c2 + 1];
            sc[j][0] = sc[j][0] * 0.125f + mv0;
            sc[j][1] = sc[j][1] * 0.125f + mv1;
            sc[j][2] = sc[j][2] * 0.125f + mv0;
            sc[j][3] = sc[j][3] * 0.125f + mv1;
            rmax0 = fmaxf(rmax0, fmaxf(sc[j][0], sc[j][1]));
            rmax1 = fmaxf(rmax1, fmaxf(sc[j][2], sc[j][3]));
        }
#pragma unroll
        for (int off = 1; off <= 2; off <<= 1) {
            rmax0 = fmaxf(rmax0, __shfl_xor_sync(0xffffffffu, rmax0, off));
            rmax1 = fmaxf(rmax1, __shfl_xor_sync(0xffffffffu, rmax1, off));
        }
        const float nm0 = fmaxf(m0, rmax0);
        const float nm1 = fmaxf(m1, rmax1);
        const float a0 = __expf(m0 - nm0);
        const float a1 = __expf(m1 - nm1);

        float rs0 = 0.0f, rs1 = 0.0f;
#pragma unroll
        for (int j = 0; j < 8; j++) {
            sc[j][0] = __expf(sc[j][0] - nm0);
            sc[j][1] = __expf(sc[j][1] - nm0);
            sc[j][2] = __expf(sc[j][2] - nm1);
            sc[j][3] = __expf(sc[j][3] - nm1);
            rs0 += sc[j][0] + sc[j][1];
            rs1 += sc[j][2] + sc[j][3];
        }
#pragma unroll
        for (int off = 1; off <= 2; off <<= 1) {
            rs0 += __shfl_xor_sync(0xffffffffu, rs0, off);
            rs1 += __shfl_xor_sync(0xffffffffu, rs1, off);
        }
        l0 = l0 * a0 + rs0;
        l1 = l1 * a1 + rs1;
        m0 = nm0;
        m1 = nm1;
#pragma unroll
        for (int j = 0; j < 8; j++) {
            o[j][0] *= a0; o[j][1] *= a0;
            o[j][2] *= a1; o[j][3] *= a1;
        }

        // ---- pack P -> A fragments (split) ----
        uint32_t ph[4][4], pl[4][4];
#pragma unroll
        for (int s = 0; s < 4; s++) {
            pack_split(sc[2 * s][0],     sc[2 * s][1],     ph[s][0], pl[s][0]);
            pack_split(sc[2 * s][2],     sc[2 * s][3],     ph[s][1], pl[s][1]);
            pack_split(sc[2 * s + 1][0], sc[2 * s + 1][1], ph[s][2], pl[s][2]);
            pack_split(sc[2 * s + 1][2], sc[2 * s + 1][3], ph[s][3], pl[s][3]);
        }

        // ---- O += P V (split, 3 passes), ldmatrix V frags ----
#pragma unroll
        for (int s = 0; s < 4; s++) {
#pragma unroll
            for (int p = 0; p < 4; p++) {
                uint32_t bh[4], bl[4];
                ldsm_x4(bh[0], bh[1], bh[2], bh[3], sbVh + offKV[p] + s * 32);
                ldsm_x4(bl[0], bl[1], bl[2], bl[3], sbVl + offKV[p] + s * 32);
#pragma unroll
                for (int t = 0; t < 2; t++) {
                    const int j = 2 * p + t;
                    mma_bf16(o[j][0], o[j][1], o[j][2], o[j][3],
                             ph[s][0], ph[s][1], ph[s][2], ph[s][3], bh[2 * t], bh[2 * t + 1]);
                    mma_bf16(o[j][0], o[j][1], o[j][2], o[j][3],
                             ph[s][0], ph[s][1], ph[s][2], ph[s][3], bl[2 * t], bl[2 * t + 1]);
                    mma_bf16(o[j][0], o[j][1], o[j][2], o[j][3],
                             pl[s][0], pl[s][1], pl[s][2], pl[s][3], bh[2 * t], bh[2 * t + 1]);
                }
            }
        }
    }

    // ---- finalize + store split-bf16 ctx ----
    const float inv0 = 1.0f / l0;
    const float inv1 = 1.0f / l1;
    const size_t r0 = row_base + q0 + wid * 16 + g;
    const size_t r1 = r0 + 8;
#pragma unroll
    for (int j = 0; j < 8; j++) {
        uint32_t h0, lo0, h1, lo1;
        pack_split(o[j][0] * inv0, o[j][1] * inv0, h0, lo0);
        pack_split(o[j][2] * inv1, o[j][3] * inv1, h1, lo1);
        const size_t o0 = r0 * HID + hoff + j * 8 + c2;
        const size_t o1 = r1 * HID + hoff + j * 8 + c2;
        *(uint32_t*)(ctxh + o0) = h0;
        *(uint32_t*)(ctxl + o0) = lo0;
        *(uint32_t*)(ctxh + o1) = h1;
        *(uint32_t*)(ctxl + o1) = lo1;
    }
}

// ---------------------------------------------------------------------------
extern "C" void kernel_launch(void* const* d_in, const int* in_sizes, int n_in,
                              void* d_out, int out_size)
{
    const float* hidden = (const float*)d_in[0];
    const float* mask   = (const float*)d_in[1];
    const float* w_attn = (const float*)d_in[2];
    const float* b_attn = (const float*)d_in[3];
    const float* w_proj = (const float*)d_in[4];
    const float* b_proj = (const float*)d_in[5];
    float* out = (float*)d_out;

    __nv_bfloat16 *hh, *hl, *qkvh, *qkvl, *ctxh, *ctxl, *vTh, *vTl, *wTh, *wTl, *pTh, *pTl;
    cudaGetSymbolAddress((void**)&hh,   g_hh);
    cudaGetSymbolAddress((void**)&hl,   g_hl);
    cudaGetSymbolAddress((void**)&qkvh, g_qkvh);
    cudaGetSymbolAddress((void**)&qkvl, g_qkvl);
    cudaGetSymbolAddress((void**)&ctxh, g_ctxh);
    cudaGetSymbolAddress((void**)&ctxl, g_ctxl);
    cudaGetSymbolAddress((void**)&vTh,  g_vTh);
    cudaGetSymbolAddress((void**)&vTl,  g_vTl);
    cudaGetSymbolAddress((void**)&wTh,  g_wTh);
    cudaGetSymbolAddress((void**)&wTl,  g_wTl);
    cudaGetSymbolAddress((void**)&pTh,  g_pTh);
    cudaGetSymbolAddress((void**)&pTl,  g_pTl);

    static bool attr_set = false;
    if (!attr_set) {
        cudaFuncSetAttribute(flash_attn_tc,
                             cudaFuncAttributeMaxDynamicSharedMemorySize, SMEM_TOT);
        cudaFuncSetAttribute(gemm_bf16_pipe,
                             cudaFuncAttributeMaxDynamicSharedMemorySize, G_SMEM);
        attr_set = true;
    }

    // 0) Prep
    transpose_split<<<dim3(QKV_N / 32, HID / 32), dim3(32, 8)>>>(w_attn, wTh, wTl, HID, QKV_N);
    transpose_split<<<dim3(HID / 32, HID / 32), dim3(32, 8)>>>(w_proj, pTh, pTl, HID, HID);
    split_act<<<(M_TOT * HID) / 1024, 256>>>(hidden, hh, hl);

    // 1) QKV GEMM -> split-bf16 qkv
    gemm_bf16_pipe<<<dim3(QKV_N / 128, M_TOT / 128), 256, G_SMEM>>>(
        hh, hl, wTh, wTl, b_attn, nullptr, qkvh, qkvl, HID, QKV_N);

    // 1b) V transpose
    transpose_v<<<dim3(SEQ / 32, HID / 32, BATCH), dim3(32, 8)>>>(qkvh, qkvl, vTh, vTl);

    // 2) Flash attention -> split-bf16 ctx
    flash_attn_tc<<<dim3(SEQ / 128, NHEAD, BATCH), 256, SMEM_TOT>>>(
        qkvh, qkvl, vTh, vTl, mask, ctxh, ctxl);

    // 3) out = ctx @ c_proj_w + b
    gemm_bf16_pipe<<<dim3(HID / 128, M_TOT / 128), 256, G_SMEM>>>(
        ctxh, ctxl, pTh, pTl, b_proj, out, nullptr, nullptr, HID, HID);
}